// round 1
// baseline (speedup 1.0000x reference)
#include <cuda_runtime.h>
#include <math.h>
#include <float.h>

#define BATCH 2
#define CCH   512
#define HW    4096
#define NGRP  32
#define CPG   16
#define GRPELEM (CPG * HW)   // 65536

// ---------------- scratch (static device globals; no allocation) -------------
__device__ float g_hn[(size_t)BATCH * CCH * HW];   // normed, [b][c][n]   16 MB
__device__ float g_q [(size_t)BATCH * HW * CCH];   // [b][i][c]           16 MB
__device__ float g_k [(size_t)BATCH * HW * CCH];   // [b][j][c]           16 MB
__device__ float g_v [(size_t)BATCH * HW * CCH];   // [b][i][c]           16 MB
__device__ float g_s [(size_t)BATCH * HW * HW];    // scores/softmax     134 MB
__device__ float g_o [(size_t)BATCH * HW * CCH];   // attn out [b][j][c]  16 MB

// ---------------------------- GroupNorm --------------------------------------
__global__ void groupnorm_kernel(const float* __restrict__ x,
                                 const float* __restrict__ gw,
                                 const float* __restrict__ gb) {
    int b = blockIdx.x >> 5;
    int g = blockIdx.x & 31;
    const float4* xp = (const float4*)(x    + ((size_t)b * CCH + g * CPG) * HW);
    float4*       op = (float4*)      (g_hn + ((size_t)b * CCH + g * CPG) * HW);
    int tid = threadIdx.x;

    float s = 0.f, ss = 0.f;
    for (int i = tid; i < GRPELEM / 4; i += 256) {
        float4 v = xp[i];
        s  += v.x + v.y + v.z + v.w;
        ss += v.x * v.x + v.y * v.y + v.z * v.z + v.w * v.w;
    }
    __shared__ float shs[8], shss[8];
    #pragma unroll
    for (int o = 16; o; o >>= 1) {
        s  += __shfl_xor_sync(0xffffffffu, s,  o);
        ss += __shfl_xor_sync(0xffffffffu, ss, o);
    }
    if ((tid & 31) == 0) { shs[tid >> 5] = s; shss[tid >> 5] = ss; }
    __syncthreads();
    __shared__ float sm, sr;
    if (tid == 0) {
        float S = 0.f, SS = 0.f;
        #pragma unroll
        for (int i = 0; i < 8; i++) { S += shs[i]; SS += shss[i]; }
        float mean = S / (float)GRPELEM;
        float var  = SS / (float)GRPELEM - mean * mean;
        sm = mean;
        sr = rsqrtf(var + 1e-6f);
    }
    __syncthreads();
    float mean = sm, rstd = sr;
    for (int i = tid; i < GRPELEM / 4; i += 256) {
        int cl = i >> 10;                         // 1024 float4 per channel
        float sc = gw[g * CPG + cl] * rstd;
        float sh = gb[g * CPG + cl] - mean * sc;
        float4 v = xp[i];
        v.x = v.x * sc + sh; v.y = v.y * sc + sh;
        v.z = v.z * sc + sh; v.w = v.w * sc + sh;
        op[i] = v;
    }
}

// ------------------- QKV GEMM: C[m,n] = sum_k A[k,m] * W[n,k] + bias[n] ------
// A = g_hn (col-major-in-m, k = channel), W row-major [out, in], out [b][m][n]
__global__ __launch_bounds__(256, 2)
void gemm_qkv_kernel(const float* __restrict__ Wt,
                     const float* __restrict__ bias, int which) {
    __shared__ float As[8][128];
    __shared__ float Bs[8][128];
    int b = blockIdx.z;
    const float* A  = g_hn + (size_t)b * CCH * HW;
    float* Cp = (which == 0 ? g_q : which == 1 ? g_k : g_v) + (size_t)b * HW * CCH;
    int m0 = blockIdx.x * 128, n0 = blockIdx.y * 128;
    int tid = threadIdx.x;
    int a_kk = tid >> 5, a_mm = (tid & 31) << 2;
    int b_nn = tid >> 1, b_k4 = (tid & 1) << 2;
    int tr = (tid >> 4) << 3, tc = (tid & 15) << 3;
    float acc[8][8];
    #pragma unroll
    for (int i = 0; i < 8; i++)
        #pragma unroll
        for (int j = 0; j < 8; j++) acc[i][j] = 0.f;

    for (int k0 = 0; k0 < CCH; k0 += 8) {
        *(float4*)&As[a_kk][a_mm] =
            *(const float4*)(A + (size_t)(k0 + a_kk) * HW + m0 + a_mm);
        float4 bv = *(const float4*)(Wt + (size_t)(n0 + b_nn) * CCH + k0 + b_k4);
        Bs[b_k4 + 0][b_nn] = bv.x; Bs[b_k4 + 1][b_nn] = bv.y;
        Bs[b_k4 + 2][b_nn] = bv.z; Bs[b_k4 + 3][b_nn] = bv.w;
        __syncthreads();
        #pragma unroll
        for (int kk = 0; kk < 8; kk++) {
            float ar[8], br[8];
            *(float4*)ar       = *(float4*)&As[kk][tr];
            *(float4*)(ar + 4) = *(float4*)&As[kk][tr + 4];
            *(float4*)br       = *(float4*)&Bs[kk][tc];
            *(float4*)(br + 4) = *(float4*)&Bs[kk][tc + 4];
            #pragma unroll
            for (int i = 0; i < 8; i++)
                #pragma unroll
                for (int j = 0; j < 8; j++) acc[i][j] += ar[i] * br[j];
        }
        __syncthreads();
    }
    #pragma unroll
    for (int i = 0; i < 8; i++) {
        float* orow = Cp + (size_t)(m0 + tr + i) * CCH + n0 + tc;
        #pragma unroll
        for (int j = 0; j < 8; j++) orow[j] = acc[i][j] + bias[n0 + tc + j];
    }
}

// -------- Scores: S[i,j] = scale * sum_c Q[i,c]*K[j,c]  (both K-contiguous) --
__global__ __launch_bounds__(256, 2)
void gemm_scores_kernel() {
    __shared__ float As[8][128];
    __shared__ float Bs[8][128];
    int b = blockIdx.z;
    const float* Aq = g_q + (size_t)b * HW * CCH;
    const float* Bk = g_k + (size_t)b * HW * CCH;
    float* Cp = g_s + (size_t)b * HW * HW;
    int m0 = blockIdx.x * 128, n0 = blockIdx.y * 128;
    int tid = threadIdx.x;
    int l_r = tid >> 1, l_k4 = (tid & 1) << 2;
    int tr = (tid >> 4) << 3, tc = (tid & 15) << 3;
    float acc[8][8];
    #pragma unroll
    for (int i = 0; i < 8; i++)
        #pragma unroll
        for (int j = 0; j < 8; j++) acc[i][j] = 0.f;

    for (int k0 = 0; k0 < CCH; k0 += 8) {
        float4 av = *(const float4*)(Aq + (size_t)(m0 + l_r) * CCH + k0 + l_k4);
        As[l_k4 + 0][l_r] = av.x; As[l_k4 + 1][l_r] = av.y;
        As[l_k4 + 2][l_r] = av.z; As[l_k4 + 3][l_r] = av.w;
        float4 bv = *(const float4*)(Bk + (size_t)(n0 + l_r) * CCH + k0 + l_k4);
        Bs[l_k4 + 0][l_r] = bv.x; Bs[l_k4 + 1][l_r] = bv.y;
        Bs[l_k4 + 2][l_r] = bv.z; Bs[l_k4 + 3][l_r] = bv.w;
        __syncthreads();
        #pragma unroll
        for (int kk = 0; kk < 8; kk++) {
            float ar[8], br[8];
            *(float4*)ar       = *(float4*)&As[kk][tr];
            *(float4*)(ar + 4) = *(float4*)&As[kk][tr + 4];
            *(float4*)br       = *(float4*)&Bs[kk][tc];
            *(float4*)(br + 4) = *(float4*)&Bs[kk][tc + 4];
            #pragma unroll
            for (int i = 0; i < 8; i++)
                #pragma unroll
                for (int j = 0; j < 8; j++) acc[i][j] += ar[i] * br[j];
        }
        __syncthreads();
    }
    const float scale = 0.04419417382415922f;   // 512^-0.5
    #pragma unroll
    for (int i = 0; i < 8; i++) {
        float* crow = Cp + (size_t)(m0 + tr + i) * HW + n0 + tc;
        float4 s0 = make_float4(acc[i][0] * scale, acc[i][1] * scale,
                                acc[i][2] * scale, acc[i][3] * scale);
        float4 s1 = make_float4(acc[i][4] * scale, acc[i][5] * scale,
                                acc[i][6] * scale, acc[i][7] * scale);
        *(float4*)crow       = s0;
        *(float4*)(crow + 4) = s1;
    }
}

// ------------------------------ Row softmax ----------------------------------
__global__ void softmax_kernel() {
    float4* row = (float4*)(g_s + (size_t)blockIdx.x * HW);
    int tid = threadIdx.x;
    float4 v[4];
    float m = -FLT_MAX;
    #pragma unroll
    for (int t = 0; t < 4; t++) {
        v[t] = row[tid + t * 256];
        m = fmaxf(m, fmaxf(fmaxf(v[t].x, v[t].y), fmaxf(v[t].z, v[t].w)));
    }
    __shared__ float shm[8];
    #pragma unroll
    for (int o = 16; o; o >>= 1) m = fmaxf(m, __shfl_xor_sync(0xffffffffu, m, o));
    if ((tid & 31) == 0) shm[tid >> 5] = m;
    __syncthreads();
    __shared__ float bcastM;
    if (tid == 0) {
        float t = shm[0];
        #pragma unroll
        for (int i = 1; i < 8; i++) t = fmaxf(t, shm[i]);
        bcastM = t;
    }
    __syncthreads();
    float M = bcastM;
    float sum = 0.f;
    #pragma unroll
    for (int t = 0; t < 4; t++) {
        v[t].x = __expf(v[t].x - M); v[t].y = __expf(v[t].y - M);
        v[t].z = __expf(v[t].z - M); v[t].w = __expf(v[t].w - M);
        sum += v[t].x + v[t].y + v[t].z + v[t].w;
    }
    __shared__ float shs[8];
    #pragma unroll
    for (int o = 16; o; o >>= 1) sum += __shfl_xor_sync(0xffffffffu, sum, o);
    if ((tid & 31) == 0) shs[tid >> 5] = sum;
    __syncthreads();
    __shared__ float bcastR;
    if (tid == 0) {
        float t = 0.f;
        #pragma unroll
        for (int i = 0; i < 8; i++) t += shs[i];
        bcastR = __fdividef(1.f, t);
    }
    __syncthreads();
    float r = bcastR;
    #pragma unroll
    for (int t = 0; t < 4; t++) {
        v[t].x *= r; v[t].y *= r; v[t].z *= r; v[t].w *= r;
        row[tid + t * 256] = v[t];
    }
}

// ----- O GEMM: O[j,c] = sum_i W[i,j] * V[i,c]   (A col-major, B row-major) ---
__global__ __launch_bounds__(256, 2)
void gemm_o_kernel() {
    __shared__ float As[8][128];
    __shared__ float Bs[8][128];
    int b = blockIdx.z;
    const float* A  = g_s + (size_t)b * HW * HW;
    const float* Bv = g_v + (size_t)b * HW * CCH;
    float* Cp = g_o + (size_t)b * HW * CCH;
    int m0 = blockIdx.x * 128, n0 = blockIdx.y * 128;
    int tid = threadIdx.x;
    int a_kk = tid >> 5, a_mm = (tid & 31) << 2;
    int tr = (tid >> 4) << 3, tc = (tid & 15) << 3;
    float acc[8][8];
    #pragma unroll
    for (int i = 0; i < 8; i++)
        #pragma unroll
        for (int j = 0; j < 8; j++) acc[i][j] = 0.f;

    for (int k0 = 0; k0 < HW; k0 += 8) {
        *(float4*)&As[a_kk][a_mm] =
            *(const float4*)(A + (size_t)(k0 + a_kk) * HW + m0 + a_mm);
        *(float4*)&Bs[a_kk][a_mm] =
            *(const float4*)(Bv + (size_t)(k0 + a_kk) * CCH + n0 + a_mm);
        __syncthreads();
        #pragma unroll
        for (int kk = 0; kk < 8; kk++) {
            float ar[8], br[8];
            *(float4*)ar       = *(float4*)&As[kk][tr];
            *(float4*)(ar + 4) = *(float4*)&As[kk][tr + 4];
            *(float4*)br       = *(float4*)&Bs[kk][tc];
            *(float4*)(br + 4) = *(float4*)&Bs[kk][tc + 4];
            #pragma unroll
            for (int i = 0; i < 8; i++)
                #pragma unroll
                for (int j = 0; j < 8; j++) acc[i][j] += ar[i] * br[j];
        }
        __syncthreads();
    }
    #pragma unroll
    for (int i = 0; i < 8; i++) {
        float* crow = Cp + (size_t)(m0 + tr + i) * CCH + n0 + tc;
        *(float4*)crow       = make_float4(acc[i][0], acc[i][1], acc[i][2], acc[i][3]);
        *(float4*)(crow + 4) = make_float4(acc[i][4], acc[i][5], acc[i][6], acc[i][7]);
    }
}

// ------ Proj + residual: out[b,o,n] = x[b,o,n] + sum_c O[n,c]*Wp[o,c] + bp[o]
__global__ __launch_bounds__(256, 2)
void gemm_proj_kernel(const float* __restrict__ Wp, const float* __restrict__ bp,
                      const float* __restrict__ x, float* __restrict__ out) {
    __shared__ float As[8][128];
    __shared__ float Bs[8][128];
    int b = blockIdx.z;
    const float* A  = g_o + (size_t)b * HW * CCH;
    const float* xb = x   + (size_t)b * CCH * HW;
    float* ob = out + (size_t)b * CCH * HW;
    int m0 = blockIdx.x * 128, n0 = blockIdx.y * 128;
    int tid = threadIdx.x;
    int l_r = tid >> 1, l_k4 = (tid & 1) << 2;
    int tr = (tid >> 4) << 3, tc = (tid & 15) << 3;
    float acc[8][8];
    #pragma unroll
    for (int i = 0; i < 8; i++)
        #pragma unroll
        for (int j = 0; j < 8; j++) acc[i][j] = 0.f;

    for (int k0 = 0; k0 < CCH; k0 += 8) {
        float4 av = *(const float4*)(A + (size_t)(m0 + l_r) * CCH + k0 + l_k4);
        As[l_k4 + 0][l_r] = av.x; As[l_k4 + 1][l_r] = av.y;
        As[l_k4 + 2][l_r] = av.z; As[l_k4 + 3][l_r] = av.w;
        float4 bv = *(const float4*)(Wp + (size_t)(n0 + l_r) * CCH + k0 + l_k4);
        Bs[l_k4 + 0][l_r] = bv.x; Bs[l_k4 + 1][l_r] = bv.y;
        Bs[l_k4 + 2][l_r] = bv.z; Bs[l_k4 + 3][l_r] = bv.w;
        __syncthreads();
        #pragma unroll
        for (int kk = 0; kk < 8; kk++) {
            float ar[8], br[8];
            *(float4*)ar       = *(float4*)&As[kk][tr];
            *(float4*)(ar + 4) = *(float4*)&As[kk][tr + 4];
            *(float4*)br       = *(float4*)&Bs[kk][tc];
            *(float4*)(br + 4) = *(float4*)&Bs[kk][tc + 4];
            #pragma unroll
            for (int i = 0; i < 8; i++)
                #pragma unroll
                for (int j = 0; j < 8; j++) acc[i][j] += ar[i] * br[j];
        }
        __syncthreads();
    }
    #pragma unroll
    for (int j = 0; j < 8; j++) {
        int o = n0 + tc + j;
        float bv = bp[o];
        const float* xr = xb + (size_t)o * HW + m0 + tr;
        float*       orw = ob + (size_t)o * HW + m0 + tr;
        #pragma unroll
        for (int i = 0; i < 8; i++) orw[i] = xr[i] + acc[i][j] + bv;
    }
}

// ------------------------------ launch ---------------------------------------
extern "C" void kernel_launch(void* const* d_in, const int* in_sizes, int n_in,
                              void* d_out, int out_size) {
    const float* x  = (const float*)d_in[0];
    const float* nw = (const float*)d_in[1];
    const float* nb = (const float*)d_in[2];
    const float* wq = (const float*)d_in[3];
    const float* bq = (const float*)d_in[4];
    const float* wk = (const float*)d_in[5];
    const float* bk = (const float*)d_in[6];
    const float* wv = (const float*)d_in[7];
    const float* bv = (const float*)d_in[8];
    const float* wp = (const float*)d_in[9];
    const float* bp = (const float*)d_in[10];
    float* out = (float*)d_out;

    groupnorm_kernel<<<BATCH * NGRP, 256>>>(x, nw, nb);

    dim3 gqkv(HW / 128, CCH / 128, BATCH);      // 32 x 4 x 2
    gemm_qkv_kernel<<<gqkv, 256>>>(wq, bq, 0);
    gemm_qkv_kernel<<<gqkv, 256>>>(wk, bk, 1);
    gemm_qkv_kernel<<<gqkv, 256>>>(wv, bv, 2);

    dim3 gsc(HW / 128, HW / 128, BATCH);        // 32 x 32 x 2
    gemm_scores_kernel<<<gsc, 256>>>();

    softmax_kernel<<<BATCH * HW, 256>>>();

    gemm_o_kernel<<<gqkv, 256>>>();

    gemm_proj_kernel<<<gqkv, 256>>>(wp, bp, x, out);
}

// round 3
// speedup vs baseline: 2.6513x; 2.6513x over previous
#include <cuda_runtime.h>
#include <math.h>
#include <float.h>

#define BATCH 2
#define CCH   512
#define HW    4096
#define NGRP  32
#define CPG   16
#define GRPELEM (CPG * HW)   // 65536

#define PMK 20    // pad for [row][k] tiles (128 x 16)
#define PKM 136   // pad for [k][col] tiles (16 x 128)

// ---------------- scratch (static device globals; no allocation) -------------
__device__ float g_hn[(size_t)BATCH * CCH * HW];   // normed, [b][c][n]
__device__ float g_q [(size_t)BATCH * HW * CCH];   // [b][i][c]
__device__ float g_k [(size_t)BATCH * HW * CCH];   // [b][j][c]
__device__ float g_v [(size_t)BATCH * HW * CCH];   // [b][i][c]
__device__ float g_s [(size_t)BATCH * HW * HW];    // scores/softmax
__device__ float g_o [(size_t)BATCH * HW * CCH];   // attn out [b][j][c]

// ------------------------------ helpers --------------------------------------
__device__ __forceinline__ unsigned f2tf(float f) {
    unsigned r;
    asm("cvt.rna.tf32.f32 %0, %1;" : "=r"(r) : "f"(f));
    return r;
}

__device__ __forceinline__ void mma8(float* d, const unsigned* a, const unsigned* b) {
    asm volatile(
        "mma.sync.aligned.m16n8k8.row.col.f32.tf32.tf32.f32 "
        "{%0,%1,%2,%3}, {%4,%5,%6,%7}, {%8,%9}, {%0,%1,%2,%3};\n"
        : "+f"(d[0]), "+f"(d[1]), "+f"(d[2]), "+f"(d[3])
        : "r"(a[0]), "r"(a[1]), "r"(a[2]), "r"(a[3]), "r"(b[0]), "r"(b[1]));
}

__device__ __forceinline__ uint4 tf4(float4 v) {
    return make_uint4(f2tf(v.x), f2tf(v.y), f2tf(v.z), f2tf(v.w));
}

// ---------------------------- GroupNorm --------------------------------------
__global__ void groupnorm_kernel(const float* __restrict__ x,
                                 const float* __restrict__ gw,
                                 const float* __restrict__ gb) {
    int b = blockIdx.x >> 5;
    int g = blockIdx.x & 31;
    const float4* xp = (const float4*)(x    + ((size_t)b * CCH + g * CPG) * HW);
    float4*       op = (float4*)      (g_hn + ((size_t)b * CCH + g * CPG) * HW);
    int tid = threadIdx.x;

    float s = 0.f, ss = 0.f;
    for (int i = tid; i < GRPELEM / 4; i += 256) {
        float4 v = xp[i];
        s  += v.x + v.y + v.z + v.w;
        ss += v.x * v.x + v.y * v.y + v.z * v.z + v.w * v.w;
    }
    __shared__ float shs[8], shss[8];
    #pragma unroll
    for (int o = 16; o; o >>= 1) {
        s  += __shfl_xor_sync(0xffffffffu, s,  o);
        ss += __shfl_xor_sync(0xffffffffu, ss, o);
    }
    if ((tid & 31) == 0) { shs[tid >> 5] = s; shss[tid >> 5] = ss; }
    __syncthreads();
    __shared__ float sm, sr;
    if (tid == 0) {
        float S = 0.f, SS = 0.f;
        #pragma unroll
        for (int i = 0; i < 8; i++) { S += shs[i]; SS += shss[i]; }
        float mean = S / (float)GRPELEM;
        float var  = SS / (float)GRPELEM - mean * mean;
        sm = mean;
        sr = rsqrtf(var + 1e-6f);
    }
    __syncthreads();
    float mean = sm, rstd = sr;
    for (int i = tid; i < GRPELEM / 4; i += 256) {
        int cl = i >> 10;
        float sc = gw[g * CPG + cl] * rstd;
        float sh = gb[g * CPG + cl] - mean * sc;
        float4 v = xp[i];
        v.x = v.x * sc + sh; v.y = v.y * sc + sh;
        v.z = v.z * sc + sh; v.w = v.w * sc + sh;
        op[i] = v;
    }
}

// -------- QKV GEMM (tf32 mma): C[m,n] = sum_k A[k,m] * W[n,k] + bias[n] ------
// A = g_hn KM-layout (stride HW), B = W MK-layout (k-contig rows)
__global__ __launch_bounds__(256)
void qkv_mma_kernel(const float* __restrict__ Wt,
                    const float* __restrict__ bias, int which) {
    __shared__ unsigned As[2][16 * PKM];
    __shared__ unsigned Bs[2][128 * PMK];
    int b = blockIdx.z;
    const float* Ag = g_hn + (size_t)b * CCH * HW + blockIdx.x * 128;
    float* Cp = (which == 0 ? g_q : which == 1 ? g_k : g_v) + (size_t)b * HW * CCH;
    int n0 = blockIdx.y * 128, m0 = blockIdx.x * 128;
    int tid = threadIdx.x;
    int lane = tid & 31, warp = tid >> 5;
    int g = lane >> 2, tig = lane & 3;
    int wm = (warp >> 2) * 64, wn = (warp & 3) * 32;
    int lkk = tid >> 4, lm = (tid & 15) * 8;   // A tile: 16 k-rows x 128 m
    int lr  = tid >> 1, lk = (tid & 1) * 8;    // B tile: 128 n-rows x 16 k

    float acc[4][4][4];
    #pragma unroll
    for (int i = 0; i < 4; i++)
        #pragma unroll
        for (int j = 0; j < 4; j++)
            #pragma unroll
            for (int t = 0; t < 4; t++) acc[i][j][t] = 0.f;

    float4 pa0, pa1, pb0, pb1;
    pa0 = *(const float4*)(Ag + (size_t)lkk * HW + lm);
    pa1 = *(const float4*)(Ag + (size_t)lkk * HW + lm + 4);
    pb0 = *(const float4*)(Wt + (size_t)(n0 + lr) * CCH + lk);
    pb1 = *(const float4*)(Wt + (size_t)(n0 + lr) * CCH + lk + 4);
    *(uint4*)&As[0][lkk * PKM + lm]     = tf4(pa0);
    *(uint4*)&As[0][lkk * PKM + lm + 4] = tf4(pa1);
    *(uint4*)&Bs[0][lr * PMK + lk]      = tf4(pb0);
    *(uint4*)&Bs[0][lr * PMK + lk + 4]  = tf4(pb1);
    __syncthreads();

    for (int kt = 0; kt < CCH / 16; kt++) {
        int nk = (kt + 1) * 16;
        if (nk < CCH) {
            pa0 = *(const float4*)(Ag + (size_t)(nk + lkk) * HW + lm);
            pa1 = *(const float4*)(Ag + (size_t)(nk + lkk) * HW + lm + 4);
            pb0 = *(const float4*)(Wt + (size_t)(n0 + lr) * CCH + nk + lk);
            pb1 = *(const float4*)(Wt + (size_t)(n0 + lr) * CCH + nk + lk + 4);
        }
        int cb = kt & 1;
        #pragma unroll
        for (int kk = 0; kk < 16; kk += 8) {
            unsigned af[4][4], bf[4][2];
            #pragma unroll
            for (int mi = 0; mi < 4; mi++) {
                int mb = wm + mi * 16 + g;
                af[mi][0] = As[cb][(kk + tig) * PKM + mb];
                af[mi][1] = As[cb][(kk + tig) * PKM + mb + 8];
                af[mi][2] = As[cb][(kk + tig + 4) * PKM + mb];
                af[mi][3] = As[cb][(kk + tig + 4) * PKM + mb + 8];
            }
            #pragma unroll
            for (int nj = 0; nj < 4; nj++) {
                int nb = wn + nj * 8 + g;
                bf[nj][0] = Bs[cb][nb * PMK + kk + tig];
                bf[nj][1] = Bs[cb][nb * PMK + kk + tig + 4];
            }
            #pragma unroll
            for (int mi = 0; mi < 4; mi++)
                #pragma unroll
                for (int nj = 0; nj < 4; nj++) mma8(acc[mi][nj], af[mi], bf[nj]);
        }
        if (nk < CCH) {
            int nb2 = cb ^ 1;
            *(uint4*)&As[nb2][lkk * PKM + lm]     = tf4(pa0);
            *(uint4*)&As[nb2][lkk * PKM + lm + 4] = tf4(pa1);
            *(uint4*)&Bs[nb2][lr * PMK + lk]      = tf4(pb0);
            *(uint4*)&Bs[nb2][lr * PMK + lk + 4]  = tf4(pb1);
        }
        __syncthreads();
    }
    #pragma unroll
    for (int mi = 0; mi < 4; mi++)
        #pragma unroll
        for (int nj = 0; nj < 4; nj++) {
            int r = m0 + wm + mi * 16 + g;
            int c = n0 + wn + nj * 8 + 2 * tig;
            float bv0 = bias[c], bv1 = bias[c + 1];
            *(float2*)&Cp[(size_t)r * CCH + c] =
                make_float2(acc[mi][nj][0] + bv0, acc[mi][nj][1] + bv1);
            *(float2*)&Cp[(size_t)(r + 8) * CCH + c] =
                make_float2(acc[mi][nj][2] + bv0, acc[mi][nj][3] + bv1);
        }
}

// -------- Scores (tf32 mma): S[i,j] = scale * sum_c Q[i,c]*K[j,c] ------------
__global__ __launch_bounds__(256)
void scores_mma_kernel() {
    __shared__ unsigned As[2][128 * PMK];
    __shared__ unsigned Bs[2][128 * PMK];
    int b = blockIdx.z;
    const float* Ag = g_q + (size_t)b * HW * CCH + (size_t)blockIdx.x * 128 * CCH;
    const float* Bg = g_k + (size_t)b * HW * CCH + (size_t)blockIdx.y * 128 * CCH;
    int tid = threadIdx.x;
    int lane = tid & 31, warp = tid >> 5;
    int g = lane >> 2, tig = lane & 3;
    int wm = (warp >> 2) * 64, wn = (warp & 3) * 32;
    int lr = tid >> 1, lk = (tid & 1) * 8;

    float acc[4][4][4];
    #pragma unroll
    for (int i = 0; i < 4; i++)
        #pragma unroll
        for (int j = 0; j < 4; j++)
            #pragma unroll
            for (int t = 0; t < 4; t++) acc[i][j][t] = 0.f;

    float4 pa0, pa1, pb0, pb1;
    pa0 = *(const float4*)(Ag + (size_t)lr * CCH + lk);
    pa1 = *(const float4*)(Ag + (size_t)lr * CCH + lk + 4);
    pb0 = *(const float4*)(Bg + (size_t)lr * CCH + lk);
    pb1 = *(const float4*)(Bg + (size_t)lr * CCH + lk + 4);
    *(uint4*)&As[0][lr * PMK + lk]     = tf4(pa0);
    *(uint4*)&As[0][lr * PMK + lk + 4] = tf4(pa1);
    *(uint4*)&Bs[0][lr * PMK + lk]     = tf4(pb0);
    *(uint4*)&Bs[0][lr * PMK + lk + 4] = tf4(pb1);
    __syncthreads();

    for (int kt = 0; kt < CCH / 16; kt++) {
        int nk = (kt + 1) * 16;
        if (nk < CCH) {
            pa0 = *(const float4*)(Ag + (size_t)lr * CCH + nk + lk);
            pa1 = *(const float4*)(Ag + (size_t)lr * CCH + nk + lk + 4);
            pb0 = *(const float4*)(Bg + (size_t)lr * CCH + nk + lk);
            pb1 = *(const float4*)(Bg + (size_t)lr * CCH + nk + lk + 4);
        }
        int cb = kt & 1;
        #pragma unroll
        for (int kk = 0; kk < 16; kk += 8) {
            unsigned af[4][4], bf[4][2];
            #pragma unroll
            for (int mi = 0; mi < 4; mi++) {
                int mb = wm + mi * 16 + g;
                af[mi][0] = As[cb][(mb)     * PMK + kk + tig];
                af[mi][1] = As[cb][(mb + 8) * PMK + kk + tig];
                af[mi][2] = As[cb][(mb)     * PMK + kk + tig + 4];
                af[mi][3] = As[cb][(mb + 8) * PMK + kk + tig + 4];
            }
            #pragma unroll
            for (int nj = 0; nj < 4; nj++) {
                int nb = wn + nj * 8 + g;
                bf[nj][0] = Bs[cb][nb * PMK + kk + tig];
                bf[nj][1] = Bs[cb][nb * PMK + kk + tig + 4];
            }
            #pragma unroll
            for (int mi = 0; mi < 4; mi++)
                #pragma unroll
                for (int nj = 0; nj < 4; nj++) mma8(acc[mi][nj], af[mi], bf[nj]);
        }
        if (nk < CCH) {
            int nb2 = cb ^ 1;
            *(uint4*)&As[nb2][lr * PMK + lk]     = tf4(pa0);
            *(uint4*)&As[nb2][lr * PMK + lk + 4] = tf4(pa1);
            *(uint4*)&Bs[nb2][lr * PMK + lk]     = tf4(pb0);
            *(uint4*)&Bs[nb2][lr * PMK + lk + 4] = tf4(pb1);
        }
        __syncthreads();
    }
    const float scale = 0.04419417382415922f;   // 512^-0.5
    float* Cp = g_s + (size_t)b * HW * HW;
    int m0 = blockIdx.x * 128, n0 = blockIdx.y * 128;
    #pragma unroll
    for (int mi = 0; mi < 4; mi++)
        #pragma unroll
        for (int nj = 0; nj < 4; nj++) {
            int r = m0 + wm + mi * 16 + g;
            int c = n0 + wn + nj * 8 + 2 * tig;
            *(float2*)&Cp[(size_t)r * HW + c] =
                make_float2(acc[mi][nj][0] * scale, acc[mi][nj][1] * scale);
            *(float2*)&Cp[(size_t)(r + 8) * HW + c] =
                make_float2(acc[mi][nj][2] * scale, acc[mi][nj][3] * scale);
        }
}

// ------------------------------ Row softmax ----------------------------------
__global__ void softmax_kernel() {
    float4* row = (float4*)(g_s + (size_t)blockIdx.x * HW);
    int tid = threadIdx.x;
    float4 v[4];
    float m = -FLT_MAX;
    #pragma unroll
    for (int t = 0; t < 4; t++) {
        v[t] = row[tid + t * 256];
        m = fmaxf(m, fmaxf(fmaxf(v[t].x, v[t].y), fmaxf(v[t].z, v[t].w)));
    }
    __shared__ float shm[8];
    #pragma unroll
    for (int o = 16; o; o >>= 1) m = fmaxf(m, __shfl_xor_sync(0xffffffffu, m, o));
    if ((tid & 31) == 0) shm[tid >> 5] = m;
    __syncthreads();
    __shared__ float bcastM;
    if (tid == 0) {
        float t = shm[0];
        #pragma unroll
        for (int i = 1; i < 8; i++) t = fmaxf(t, shm[i]);
        bcastM = t;
    }
    __syncthreads();
    float M = bcastM;
    float sum = 0.f;
    #pragma unroll
    for (int t = 0; t < 4; t++) {
        v[t].x = __expf(v[t].x - M); v[t].y = __expf(v[t].y - M);
        v[t].z = __expf(v[t].z - M); v[t].w = __expf(v[t].w - M);
        sum += v[t].x + v[t].y + v[t].z + v[t].w;
    }
    __shared__ float shs[8];
    #pragma unroll
    for (int o = 16; o; o >>= 1) sum += __shfl_xor_sync(0xffffffffu, sum, o);
    if ((tid & 31) == 0) shs[tid >> 5] = sum;
    __syncthreads();
    __shared__ float bcastR;
    if (tid == 0) {
        float t = 0.f;
        #pragma unroll
        for (int i = 0; i < 8; i++) t += shs[i];
        bcastR = __fdividef(1.f, t);
    }
    __syncthreads();
    float r = bcastR;
    #pragma unroll
    for (int t = 0; t < 4; t++) {
        v[t].x *= r; v[t].y *= r; v[t].z *= r; v[t].w *= r;
        row[tid + t * 256] = v[t];
    }
}

// ------ O GEMM (tf32 mma): O[j,c] = sum_i W[i,j] * V[i,c] --------------------
// A = g_s KM-layout (stride HW), B = g_v KM-layout (stride CCH)
__global__ __launch_bounds__(256)
void o_mma_kernel() {
    __shared__ unsigned As[2][16 * PKM];
    __shared__ unsigned Bs[2][16 * PKM];
    int b = blockIdx.z;
    const float* Ag = g_s + (size_t)b * HW * HW + blockIdx.x * 128;
    const float* Bg = g_v + (size_t)b * HW * CCH + blockIdx.y * 128;
    int tid = threadIdx.x;
    int lane = tid & 31, warp = tid >> 5;
    int g = lane >> 2, tig = lane & 3;
    int wm = (warp >> 2) * 64, wn = (warp & 3) * 32;
    int lkk = tid >> 4, lm = (tid & 15) * 8;

    float acc[4][4][4];
    #pragma unroll
    for (int i = 0; i < 4; i++)
        #pragma unroll
        for (int j = 0; j < 4; j++)
            #pragma unroll
            for (int t = 0; t < 4; t++) acc[i][j][t] = 0.f;

    float4 pa0, pa1, pb0, pb1;
    pa0 = *(const float4*)(Ag + (size_t)lkk * HW + lm);
    pa1 = *(const float4*)(Ag + (size_t)lkk * HW + lm + 4);
    pb0 = *(const float4*)(Bg + (size_t)lkk * CCH + lm);
    pb1 = *(const float4*)(Bg + (size_t)lkk * CCH + lm + 4);
    *(uint4*)&As[0][lkk * PKM + lm]     = tf4(pa0);
    *(uint4*)&As[0][lkk * PKM + lm + 4] = tf4(pa1);
    *(uint4*)&Bs[0][lkk * PKM + lm]     = tf4(pb0);
    *(uint4*)&Bs[0][lkk * PKM + lm + 4] = tf4(pb1);
    __syncthreads();

    for (int kt = 0; kt < HW / 16; kt++) {
        int nk = (kt + 1) * 16;
        if (nk < HW) {
            pa0 = *(const float4*)(Ag + (size_t)(nk + lkk) * HW + lm);
            pa1 = *(const float4*)(Ag + (size_t)(nk + lkk) * HW + lm + 4);
            pb0 = *(const float4*)(Bg + (size_t)(nk + lkk) * CCH + lm);
            pb1 = *(const float4*)(Bg + (size_t)(nk + lkk) * CCH + lm + 4);
        }
        int cb = kt & 1;
        #pragma unroll
        for (int kk = 0; kk < 16; kk += 8) {
            unsigned af[4][4], bf[4][2];
            #pragma unroll
            for (int mi = 0; mi < 4; mi++) {
                int mb = wm + mi * 16 + g;
                af[mi][0] = As[cb][(kk + tig) * PKM + mb];
                af[mi][1] = As[cb][(kk + tig) * PKM + mb + 8];
                af[mi][2] = As[cb][(kk + tig + 4) * PKM + mb];
                af[mi][3] = As[cb][(kk + tig + 4) * PKM + mb + 8];
            }
            #pragma unroll
            for (int nj = 0; nj < 4; nj++) {
                int nb = wn + nj * 8 + g;
                bf[nj][0] = Bs[cb][(kk + tig) * PKM + nb];
                bf[nj][1] = Bs[cb][(kk + tig + 4) * PKM + nb];
            }
            #pragma unroll
            for (int mi = 0; mi < 4; mi++)
                #pragma unroll
                for (int nj = 0; nj < 4; nj++) mma8(acc[mi][nj], af[mi], bf[nj]);
        }
        if (nk < HW) {
            int nb2 = cb ^ 1;
            *(uint4*)&As[nb2][lkk * PKM + lm]     = tf4(pa0);
            *(uint4*)&As[nb2][lkk * PKM + lm + 4] = tf4(pa1);
            *(uint4*)&Bs[nb2][lkk * PKM + lm]     = tf4(pb0);
            *(uint4*)&Bs[nb2][lkk * PKM + lm + 4] = tf4(pb1);
        }
        __syncthreads();
    }
    float* Cp = g_o + (size_t)b * HW * CCH;
    int m0 = blockIdx.x * 128, n0 = blockIdx.y * 128;
    #pragma unroll
    for (int mi = 0; mi < 4; mi++)
        #pragma unroll
        for (int nj = 0; nj < 4; nj++) {
            int r = m0 + wm + mi * 16 + g;
            int c = n0 + wn + nj * 8 + 2 * tig;
            *(float2*)&Cp[(size_t)r * CCH + c] =
                make_float2(acc[mi][nj][0], acc[mi][nj][1]);
            *(float2*)&Cp[(size_t)(r + 8) * CCH + c] =
                make_float2(acc[mi][nj][2], acc[mi][nj][3]);
        }
}

// ------ Proj+residual (tf32 mma): out[o,m] = x[o,m] + sum_c O[m,c]Wp[o,c]+bp[o]
__global__ __launch_bounds__(256)
void proj_mma_kernel(const float* __restrict__ Wp, const float* __restrict__ bp,
                     const float* __restrict__ x, float* __restrict__ out) {
    __shared__ unsigned As[2][128 * PMK];
    __shared__ unsigned Bs[2][128 * PMK];
    int b = blockIdx.z;
    const float* Ag = g_o + (size_t)b * HW * CCH + (size_t)blockIdx.x * 128 * CCH;
    const float* xb = x   + (size_t)b * CCH * HW;
    float* ob = out + (size_t)b * CCH * HW;
    int n0 = blockIdx.y * 128, m0 = blockIdx.x * 128;
    int tid = threadIdx.x;
    int lane = tid & 31, warp = tid >> 5;
    int g = lane >> 2, tig = lane & 3;
    int wm = (warp >> 2) * 64, wn = (warp & 3) * 32;
    int lr = tid >> 1, lk = (tid & 1) * 8;

    float acc[4][4][4];
    #pragma unroll
    for (int i = 0; i < 4; i++)
        #pragma unroll
        for (int j = 0; j < 4; j++)
            #pragma unroll
            for (int t = 0; t < 4; t++) acc[i][j][t] = 0.f;

    float4 pa0, pa1, pb0, pb1;
    pa0 = *(const float4*)(Ag + (size_t)lr * CCH + lk);
    pa1 = *(const float4*)(Ag + (size_t)lr * CCH + lk + 4);
    pb0 = *(const float4*)(Wp + (size_t)(n0 + lr) * CCH + lk);
    pb1 = *(const float4*)(Wp + (size_t)(n0 + lr) * CCH + lk + 4);
    *(uint4*)&As[0][lr * PMK + lk]     = tf4(pa0);
    *(uint4*)&As[0][lr * PMK + lk + 4] = tf4(pa1);
    *(uint4*)&Bs[0][lr * PMK + lk]     = tf4(pb0);
    *(uint4*)&Bs[0][lr * PMK + lk + 4] = tf4(pb1);
    __syncthreads();

    for (int kt = 0; kt < CCH / 16; kt++) {
        int nk = (kt + 1) * 16;
        if (nk < CCH) {
            pa0 = *(const float4*)(Ag + (size_t)lr * CCH + nk + lk);
            pa1 = *(const float4*)(Ag + (size_t)lr * CCH + nk + lk + 4);
            pb0 = *(const float4*)(Wp + (size_t)(n0 + lr) * CCH + nk + lk);
            pb1 = *(const float4*)(Wp + (size_t)(n0 + lr) * CCH + nk + lk + 4);
        }
        int cb = kt & 1;
        #pragma unroll
        for (int kk = 0; kk < 16; kk += 8) {
            unsigned af[4][4], bf[4][2];
            #pragma unroll
            for (int mi = 0; mi < 4; mi++) {
                int mb = wm + mi * 16 + g;
                af[mi][0] = As[cb][(mb)     * PMK + kk + tig];
                af[mi][1] = As[cb][(mb + 8) * PMK + kk + tig];
                af[mi][2] = As[cb][(mb)     * PMK + kk + tig + 4];
                af[mi][3] = As[cb][(mb + 8) * PMK + kk + tig + 4];
            }
            #pragma unroll
            for (int nj = 0; nj < 4; nj++) {
                int nb = wn + nj * 8 + g;
                bf[nj][0] = Bs[cb][nb * PMK + kk + tig];
                bf[nj][1] = Bs[cb][nb * PMK + kk + tig + 4];
            }
            #pragma unroll
            for (int mi = 0; mi < 4; mi++)
                #pragma unroll
                for (int nj = 0; nj < 4; nj++) mma8(acc[mi][nj], af[mi], bf[nj]);
        }
        if (nk < CCH) {
            int nb2 = cb ^ 1;
            *(uint4*)&As[nb2][lr * PMK + lk]     = tf4(pa0);
            *(uint4*)&As[nb2][lr * PMK + lk + 4] = tf4(pa1);
            *(uint4*)&Bs[nb2][lr * PMK + lk]     = tf4(pb0);
            *(uint4*)&Bs[nb2][lr * PMK + lk + 4] = tf4(pb1);
        }
        __syncthreads();
    }
    // out is [channel][spatial]: transposed scalar epilogue with residual + bias
    #pragma unroll
    for (int nj = 0; nj < 4; nj++) {
        int c0 = n0 + wn + nj * 8 + 2 * tig;
        float bv0 = bp[c0], bv1 = bp[c0 + 1];
        #pragma unroll
        for (int mi = 0; mi < 4; mi++) {
            int r = m0 + wm + mi * 16 + g;
            ob[(size_t)c0 * HW + r]           = xb[(size_t)c0 * HW + r]           + acc[mi][nj][0] + bv0;
            ob[(size_t)(c0 + 1) * HW + r]     = xb[(size_t)(c0 + 1) * HW + r]     + acc[mi][nj][1] + bv1;
            ob[(size_t)c0 * HW + r + 8]       = xb[(size_t)c0 * HW + r + 8]       + acc[mi][nj][2] + bv0;
            ob[(size_t)(c0 + 1) * HW + r + 8] = xb[(size_t)(c0 + 1) * HW + r + 8] + acc[mi][nj][3] + bv1;
        }
    }
}

// ------------------------------ launch ---------------------------------------
extern "C" void kernel_launch(void* const* d_in, const int* in_sizes, int n_in,
                              void* d_out, int out_size) {
    const float* x  = (const float*)d_in[0];
    const float* nw = (const float*)d_in[1];
    const float* nb = (const float*)d_in[2];
    const float* wq = (const float*)d_in[3];
    const float* bq = (const float*)d_in[4];
    const float* wk = (const float*)d_in[5];
    const float* bk = (const float*)d_in[6];
    const float* wv = (const float*)d_in[7];
    const float* bv = (const float*)d_in[8];
    const float* wp = (const float*)d_in[9];
    const float* bp = (const float*)d_in[10];
    float* out = (float*)d_out;

    groupnorm_kernel<<<BATCH * NGRP, 256>>>(x, nw, nb);

    dim3 gqkv(HW / 128, CCH / 128, BATCH);      // 32 x 4 x 2
    qkv_mma_kernel<<<gqkv, 256>>>(wq, bq, 0);
    qkv_mma_kernel<<<gqkv, 256>>>(wk, bk, 1);
    qkv_mma_kernel<<<gqkv, 256>>>(wv, bv, 2);

    dim3 gsc(HW / 128, HW / 128, BATCH);        // 32 x 32 x 2
    scores_mma_kernel<<<gsc, 256>>>();

    softmax_kernel<<<BATCH * HW, 256>>>();

    o_mma_kernel<<<gqkv, 256>>>();

    proj_mma_kernel<<<gqkv, 256>>>(wp, bp, x, out);
}

// round 4
// speedup vs baseline: 3.1604x; 1.1920x over previous
#include <cuda_runtime.h>
#include <math.h>
#include <float.h>

#define BATCH 2
#define CCH   512
#define HW    4096
#define NGRP  32
#define CPG   16
#define GRPELEM (CPG * HW)   // 65536

#define PMK 12    // padded row length for [row][k8] tiles (128 x 8)
#define PKM 136   // padded row length for [k8][col] tiles (8 x 128)
#define NSTG 4

// ---------------- scratch (static device globals; no allocation) -------------
__device__ float g_hn[(size_t)BATCH * CCH * HW];   // normed, [b][c][n]
__device__ float g_q [(size_t)BATCH * HW * CCH];   // [b][i][c]
__device__ float g_k [(size_t)BATCH * HW * CCH];   // [b][j][c]
__device__ float g_v [(size_t)BATCH * HW * CCH];   // [b][i][c]
__device__ float g_s [(size_t)BATCH * HW * HW];    // scores/softmax
__device__ float g_o [(size_t)BATCH * HW * CCH];   // attn out [b][j][c]

// ------------------------------ helpers --------------------------------------
__device__ __forceinline__ void mma8(float* d, const unsigned* a, const unsigned* b) {
    asm volatile(
        "mma.sync.aligned.m16n8k8.row.col.f32.tf32.tf32.f32 "
        "{%0,%1,%2,%3}, {%4,%5,%6,%7}, {%8,%9}, {%0,%1,%2,%3};\n"
        : "+f"(d[0]), "+f"(d[1]), "+f"(d[2]), "+f"(d[3])
        : "r"(a[0]), "r"(a[1]), "r"(a[2]), "r"(a[3]), "r"(b[0]), "r"(b[1]));
}

__device__ __forceinline__ unsigned sptr(const void* p) {
    return (unsigned)__cvta_generic_to_shared(p);
}
#define CPA16(dst, src) asm volatile("cp.async.ca.shared.global [%0], [%1], 16;\n" :: "r"(dst), "l"(src))
#define CPCOMMIT()      asm volatile("cp.async.commit_group;\n")
#define CPWAIT2()       asm volatile("cp.async.wait_group 2;\n")

__device__ __forceinline__ unsigned fu(float f) { return __float_as_uint(f); }

// ---------------------------- GroupNorm --------------------------------------
__global__ void groupnorm_kernel(const float* __restrict__ x,
                                 const float* __restrict__ gw,
                                 const float* __restrict__ gb) {
    int b = blockIdx.x >> 5;
    int g = blockIdx.x & 31;
    const float4* xp = (const float4*)(x    + ((size_t)b * CCH + g * CPG) * HW);
    float4*       op = (float4*)      (g_hn + ((size_t)b * CCH + g * CPG) * HW);
    int tid = threadIdx.x;

    float s = 0.f, ss = 0.f;
    for (int i = tid; i < GRPELEM / 4; i += 256) {
        float4 v = xp[i];
        s  += v.x + v.y + v.z + v.w;
        ss += v.x * v.x + v.y * v.y + v.z * v.z + v.w * v.w;
    }
    __shared__ float shs[8], shss[8];
    #pragma unroll
    for (int o = 16; o; o >>= 1) {
        s  += __shfl_xor_sync(0xffffffffu, s,  o);
        ss += __shfl_xor_sync(0xffffffffu, ss, o);
    }
    if ((tid & 31) == 0) { shs[tid >> 5] = s; shss[tid >> 5] = ss; }
    __syncthreads();
    __shared__ float sm, sr;
    if (tid == 0) {
        float S = 0.f, SS = 0.f;
        #pragma unroll
        for (int i = 0; i < 8; i++) { S += shs[i]; SS += shss[i]; }
        float mean = S / (float)GRPELEM;
        float var  = SS / (float)GRPELEM - mean * mean;
        sm = mean;
        sr = rsqrtf(var + 1e-6f);
    }
    __syncthreads();
    float mean = sm, rstd = sr;
    for (int i = tid; i < GRPELEM / 4; i += 256) {
        int cl = i >> 10;
        float sc = gw[g * CPG + cl] * rstd;
        float sh = gb[g * CPG + cl] - mean * sc;
        float4 v = xp[i];
        v.x = v.x * sc + sh; v.y = v.y * sc + sh;
        v.z = v.z * sc + sh; v.w = v.w * sc + sh;
        op[i] = v;
    }
}

// -------- QKV GEMM: C[m,n] = sum_k A[k,m] * W[n,k] + bias[n] -----------------
// A = g_hn KM-layout (stride HW), B = W MK-layout (k-contig rows)
__global__ __launch_bounds__(256)
void qkv_mma_kernel(const float* __restrict__ Wt,
                    const float* __restrict__ bias, int which) {
    __shared__ float As[NSTG][8 * PKM];      // 4 x 4352 B
    __shared__ float Bs[NSTG][128 * PMK];    // 4 x 6144 B
    int b = blockIdx.z;
    const float* Ag = g_hn + (size_t)b * CCH * HW + blockIdx.x * 128;
    float* Cp = (which == 0 ? g_q : which == 1 ? g_k : g_v) + (size_t)b * HW * CCH;
    int n0 = blockIdx.y * 128, m0 = blockIdx.x * 128;
    int tid = threadIdx.x;
    int lane = tid & 31, warp = tid >> 5;
    int g = lane >> 2, tig = lane & 3;
    int wm = (warp >> 2) * 64, wn = (warp & 3) * 32;
    int ar = tid >> 5, ac = (tid & 31) * 4;   // A tile 8 x 128
    int br = tid >> 1, bc = (tid & 1) * 4;    // B tile 128 x 8

    float acc[4][4][4];
    #pragma unroll
    for (int i = 0; i < 4; i++)
        #pragma unroll
        for (int j = 0; j < 4; j++)
            #pragma unroll
            for (int t = 0; t < 4; t++) acc[i][j][t] = 0.f;

    const int NT = CCH / 8;
    #pragma unroll
    for (int s = 0; s < NSTG - 1; s++) {
        CPA16(sptr(&As[s][ar * PKM + ac]), Ag + (size_t)(s * 8 + ar) * HW + ac);
        CPA16(sptr(&Bs[s][br * PMK + bc]), Wt + (size_t)(n0 + br) * CCH + s * 8 + bc);
        CPCOMMIT();
    }

    for (int kt = 0; kt < NT; kt++) {
        CPWAIT2();
        __syncthreads();
        const float* Ab = As[kt & 3];
        const float* Bb = Bs[kt & 3];
        unsigned af[4][4], bf[4][2];
        #pragma unroll
        for (int mi = 0; mi < 4; mi++) {
            int mb = wm + mi * 16 + g;
            af[mi][0] = fu(Ab[tig * PKM + mb]);
            af[mi][1] = fu(Ab[tig * PKM + mb + 8]);
            af[mi][2] = fu(Ab[(tig + 4) * PKM + mb]);
            af[mi][3] = fu(Ab[(tig + 4) * PKM + mb + 8]);
        }
        #pragma unroll
        for (int nj = 0; nj < 4; nj++) {
            int nb = wn + nj * 8 + g;
            bf[nj][0] = fu(Bb[nb * PMK + tig]);
            bf[nj][1] = fu(Bb[nb * PMK + tig + 4]);
        }
        #pragma unroll
        for (int mi = 0; mi < 4; mi++)
            #pragma unroll
            for (int nj = 0; nj < 4; nj++) mma8(acc[mi][nj], af[mi], bf[nj]);
        int nk = kt + NSTG - 1;
        if (nk < NT) {
            int s = nk & 3;
            CPA16(sptr(&As[s][ar * PKM + ac]), Ag + (size_t)(nk * 8 + ar) * HW + ac);
            CPA16(sptr(&Bs[s][br * PMK + bc]), Wt + (size_t)(n0 + br) * CCH + nk * 8 + bc);
        }
        CPCOMMIT();
    }
    #pragma unroll
    for (int mi = 0; mi < 4; mi++)
        #pragma unroll
        for (int nj = 0; nj < 4; nj++) {
            int r = m0 + wm + mi * 16 + g;
            int c = n0 + wn + nj * 8 + 2 * tig;
            float bv0 = bias[c], bv1 = bias[c + 1];
            *(float2*)&Cp[(size_t)r * CCH + c] =
                make_float2(acc[mi][nj][0] + bv0, acc[mi][nj][1] + bv1);
            *(float2*)&Cp[(size_t)(r + 8) * CCH + c] =
                make_float2(acc[mi][nj][2] + bv0, acc[mi][nj][3] + bv1);
        }
}

// -------- Scores: S[i,j] = scale * sum_c Q[i,c]*K[j,c] -----------------------
__global__ __launch_bounds__(256)
void scores_mma_kernel() {
    __shared__ float As[NSTG][128 * PMK];
    __shared__ float Bs[NSTG][128 * PMK];
    int b = blockIdx.z;
    const float* Ag = g_q + (size_t)b * HW * CCH + (size_t)blockIdx.x * 128 * CCH;
    const float* Bg = g_k + (size_t)b * HW * CCH + (size_t)blockIdx.y * 128 * CCH;
    int tid = threadIdx.x;
    int lane = tid & 31, warp = tid >> 5;
    int g = lane >> 2, tig = lane & 3;
    int wm = (warp >> 2) * 64, wn = (warp & 3) * 32;
    int lr = tid >> 1, lc = (tid & 1) * 4;

    float acc[4][4][4];
    #pragma unroll
    for (int i = 0; i < 4; i++)
        #pragma unroll
        for (int j = 0; j < 4; j++)
            #pragma unroll
            for (int t = 0; t < 4; t++) acc[i][j][t] = 0.f;

    const int NT = CCH / 8;
    #pragma unroll
    for (int s = 0; s < NSTG - 1; s++) {
        CPA16(sptr(&As[s][lr * PMK + lc]), Ag + (size_t)lr * CCH + s * 8 + lc);
        CPA16(sptr(&Bs[s][lr * PMK + lc]), Bg + (size_t)lr * CCH + s * 8 + lc);
        CPCOMMIT();
    }

    for (int kt = 0; kt < NT; kt++) {
        CPWAIT2();
        __syncthreads();
        const float* Ab = As[kt & 3];
        const float* Bb = Bs[kt & 3];
        unsigned af[4][4], bf[4][2];
        #pragma unroll
        for (int mi = 0; mi < 4; mi++) {
            int mb = wm + mi * 16 + g;
            af[mi][0] = fu(Ab[mb * PMK + tig]);
            af[mi][1] = fu(Ab[(mb + 8) * PMK + tig]);
            af[mi][2] = fu(Ab[mb * PMK + tig + 4]);
            af[mi][3] = fu(Ab[(mb + 8) * PMK + tig + 4]);
        }
        #pragma unroll
        for (int nj = 0; nj < 4; nj++) {
            int nb = wn + nj * 8 + g;
            bf[nj][0] = fu(Bb[nb * PMK + tig]);
            bf[nj][1] = fu(Bb[nb * PMK + tig + 4]);
        }
        #pragma unroll
        for (int mi = 0; mi < 4; mi++)
            #pragma unroll
            for (int nj = 0; nj < 4; nj++) mma8(acc[mi][nj], af[mi], bf[nj]);
        int nk = kt + NSTG - 1;
        if (nk < NT) {
            int s = nk & 3;
            CPA16(sptr(&As[s][lr * PMK + lc]), Ag + (size_t)lr * CCH + nk * 8 + lc);
            CPA16(sptr(&Bs[s][lr * PMK + lc]), Bg + (size_t)lr * CCH + nk * 8 + lc);
        }
        CPCOMMIT();
    }
    const float scale = 0.04419417382415922f;   // 512^-0.5
    float* Cp = g_s + (size_t)b * HW * HW;
    int m0 = blockIdx.x * 128, n0 = blockIdx.y * 128;
    #pragma unroll
    for (int mi = 0; mi < 4; mi++)
        #pragma unroll
        for (int nj = 0; nj < 4; nj++) {
            int r = m0 + wm + mi * 16 + g;
            int c = n0 + wn + nj * 8 + 2 * tig;
            *(float2*)&Cp[(size_t)r * HW + c] =
                make_float2(acc[mi][nj][0] * scale, acc[mi][nj][1] * scale);
            *(float2*)&Cp[(size_t)(r + 8) * HW + c] =
                make_float2(acc[mi][nj][2] * scale, acc[mi][nj][3] * scale);
        }
}

// ------------------------------ Row softmax ----------------------------------
__global__ void softmax_kernel() {
    float4* row = (float4*)(g_s + (size_t)blockIdx.x * HW);
    int tid = threadIdx.x;
    float4 v[4];
    float m = -FLT_MAX;
    #pragma unroll
    for (int t = 0; t < 4; t++) {
        v[t] = row[tid + t * 256];
        m = fmaxf(m, fmaxf(fmaxf(v[t].x, v[t].y), fmaxf(v[t].z, v[t].w)));
    }
    __shared__ float shm[8];
    #pragma unroll
    for (int o = 16; o; o >>= 1) m = fmaxf(m, __shfl_xor_sync(0xffffffffu, m, o));
    if ((tid & 31) == 0) shm[tid >> 5] = m;
    __syncthreads();
    __shared__ float bcastM;
    if (tid == 0) {
        float t = shm[0];
        #pragma unroll
        for (int i = 1; i < 8; i++) t = fmaxf(t, shm[i]);
        bcastM = t;
    }
    __syncthreads();
    float M = bcastM;
    float sum = 0.f;
    #pragma unroll
    for (int t = 0; t < 4; t++) {
        v[t].x = __expf(v[t].x - M); v[t].y = __expf(v[t].y - M);
        v[t].z = __expf(v[t].z - M); v[t].w = __expf(v[t].w - M);
        sum += v[t].x + v[t].y + v[t].z + v[t].w;
    }
    __shared__ float shs[8];
    #pragma unroll
    for (int o = 16; o; o >>= 1) sum += __shfl_xor_sync(0xffffffffu, sum, o);
    if ((tid & 31) == 0) shs[tid >> 5] = sum;
    __syncthreads();
    __shared__ float bcastR;
    if (tid == 0) {
        float t = 0.f;
        #pragma unroll
        for (int i = 0; i < 8; i++) t += shs[i];
        bcastR = __fdividef(1.f, t);
    }
    __syncthreads();
    float r = bcastR;
    #pragma unroll
    for (int t = 0; t < 4; t++) {
        v[t].x *= r; v[t].y *= r; v[t].z *= r; v[t].w *= r;
        row[tid + t * 256] = v[t];
    }
}

// ------ O GEMM: O[j,c] = sum_i W[i,j] * V[i,c] -------------------------------
// A = g_s KM-layout (stride HW), B = g_v KM-layout (stride CCH)
__global__ __launch_bounds__(256)
void o_mma_kernel() {
    __shared__ float As[NSTG][8 * PKM];
    __shared__ float Bs[NSTG][8 * PKM];
    int b = blockIdx.z;
    const float* Ag = g_s + (size_t)b * HW * HW + blockIdx.x * 128;
    const float* Bg = g_v + (size_t)b * HW * CCH + blockIdx.y * 128;
    int tid = threadIdx.x;
    int lane = tid & 31, warp = tid >> 5;
    int g = lane >> 2, tig = lane & 3;
    int wm = (warp >> 2) * 64, wn = (warp & 3) * 32;
    int ar = tid >> 5, ac = (tid & 31) * 4;

    float acc[4][4][4];
    #pragma unroll
    for (int i = 0; i < 4; i++)
        #pragma unroll
        for (int j = 0; j < 4; j++)
            #pragma unroll
            for (int t = 0; t < 4; t++) acc[i][j][t] = 0.f;

    const int NT = HW / 8;
    #pragma unroll
    for (int s = 0; s < NSTG - 1; s++) {
        CPA16(sptr(&As[s][ar * PKM + ac]), Ag + (size_t)(s * 8 + ar) * HW + ac);
        CPA16(sptr(&Bs[s][ar * PKM + ac]), Bg + (size_t)(s * 8 + ar) * CCH + ac);
        CPCOMMIT();
    }

    for (int kt = 0; kt < NT; kt++) {
        CPWAIT2();
        __syncthreads();
        const float* Ab = As[kt & 3];
        const float* Bb = Bs[kt & 3];
        unsigned af[4][4], bf[4][2];
        #pragma unroll
        for (int mi = 0; mi < 4; mi++) {
            int mb = wm + mi * 16 + g;
            af[mi][0] = fu(Ab[tig * PKM + mb]);
            af[mi][1] = fu(Ab[tig * PKM + mb + 8]);
            af[mi][2] = fu(Ab[(tig + 4) * PKM + mb]);
            af[mi][3] = fu(Ab[(tig + 4) * PKM + mb + 8]);
        }
        #pragma unroll
        for (int nj = 0; nj < 4; nj++) {
            int nb = wn + nj * 8 + g;
            bf[nj][0] = fu(Bb[tig * PKM + nb]);
            bf[nj][1] = fu(Bb[(tig + 4) * PKM + nb]);
        }
        #pragma unroll
        for (int mi = 0; mi < 4; mi++)
            #pragma unroll
            for (int nj = 0; nj < 4; nj++) mma8(acc[mi][nj], af[mi], bf[nj]);
        int nk = kt + NSTG - 1;
        if (nk < NT) {
            int s = nk & 3;
            CPA16(sptr(&As[s][ar * PKM + ac]), Ag + (size_t)(nk * 8 + ar) * HW + ac);
            CPA16(sptr(&Bs[s][ar * PKM + ac]), Bg + (size_t)(nk * 8 + ar) * CCH + ac);
        }
        CPCOMMIT();
    }
    float* Cp = g_o + (size_t)b * HW * CCH;
    int m0 = blockIdx.x * 128, n0 = blockIdx.y * 128;
    #pragma unroll
    for (int mi = 0; mi < 4; mi++)
        #pragma unroll
        for (int nj = 0; nj < 4; nj++) {
            int r = m0 + wm + mi * 16 + g;
            int c = n0 + wn + nj * 8 + 2 * tig;
            *(float2*)&Cp[(size_t)r * CCH + c] =
                make_float2(acc[mi][nj][0], acc[mi][nj][1]);
            *(float2*)&Cp[(size_t)(r + 8) * CCH + c] =
                make_float2(acc[mi][nj][2], acc[mi][nj][3]);
        }
}

// ------ Proj+residual: out[o,m] = x[o,m] + sum_c O[m,c]Wp[o,c]+bp[o] ---------
__global__ __launch_bounds__(256)
void proj_mma_kernel(const float* __restrict__ Wp, const float* __restrict__ bp,
                     const float* __restrict__ x, float* __restrict__ out) {
    __shared__ float As[NSTG][128 * PMK];
    __shared__ float Bs[NSTG][128 * PMK];
    int b = blockIdx.z;
    const float* Ag = g_o + (size_t)b * HW * CCH + (size_t)blockIdx.x * 128 * CCH;
    const float* xb = x   + (size_t)b * CCH * HW;
    float* ob = out + (size_t)b * CCH * HW;
    int n0 = blockIdx.y * 128, m0 = blockIdx.x * 128;
    int tid = threadIdx.x;
    int lane = tid & 31, warp = tid >> 5;
    int g = lane >> 2, tig = lane & 3;
    int wm = (warp >> 2) * 64, wn = (warp & 3) * 32;
    int lr = tid >> 1, lc = (tid & 1) * 4;

    float acc[4][4][4];
    #pragma unroll
    for (int i = 0; i < 4; i++)
        #pragma unroll
        for (int j = 0; j < 4; j++)
            #pragma unroll
            for (int t = 0; t < 4; t++) acc[i][j][t] = 0.f;

    const int NT = CCH / 8;
    #pragma unroll
    for (int s = 0; s < NSTG - 1; s++) {
        CPA16(sptr(&As[s][lr * PMK + lc]), Ag + (size_t)lr * CCH + s * 8 + lc);
        CPA16(sptr(&Bs[s][lr * PMK + lc]), Wp + (size_t)(n0 + lr) * CCH + s * 8 + lc);
        CPCOMMIT();
    }

    for (int kt = 0; kt < NT; kt++) {
        CPWAIT2();
        __syncthreads();
        const float* Ab = As[kt & 3];
        const float* Bb = Bs[kt & 3];
        unsigned af[4][4], bf[4][2];
        #pragma unroll
        for (int mi = 0; mi < 4; mi++) {
            int mb = wm + mi * 16 + g;
            af[mi][0] = fu(Ab[mb * PMK + tig]);
            af[mi][1] = fu(Ab[(mb + 8) * PMK + tig]);
            af[mi][2] = fu(Ab[mb * PMK + tig + 4]);
            af[mi][3] = fu(Ab[(mb + 8) * PMK + tig + 4]);
        }
        #pragma unroll
        for (int nj = 0; nj < 4; nj++) {
            int nb = wn + nj * 8 + g;
            bf[nj][0] = fu(Bb[nb * PMK + tig]);
            bf[nj][1] = fu(Bb[nb * PMK + tig + 4]);
        }
        #pragma unroll
        for (int mi = 0; mi < 4; mi++)
            #pragma unroll
            for (int nj = 0; nj < 4; nj++) mma8(acc[mi][nj], af[mi], bf[nj]);
        int nk = kt + NSTG - 1;
        if (nk < NT) {
            int s = nk & 3;
            CPA16(sptr(&As[s][lr * PMK + lc]), Ag + (size_t)lr * CCH + nk * 8 + lc);
            CPA16(sptr(&Bs[s][lr * PMK + lc]), Wp + (size_t)(n0 + lr) * CCH + nk * 8 + lc);
        }
        CPCOMMIT();
    }
    // out is [channel][spatial]: transposed scalar epilogue with residual + bias
    #pragma unroll
    for (int nj = 0; nj < 4; nj++) {
        int c0 = n0 + wn + nj * 8 + 2 * tig;
        float bv0 = bp[c0], bv1 = bp[c0 + 1];
        #pragma unroll
        for (int mi = 0; mi < 4; mi++) {
            int r = m0 + wm + mi * 16 + g;
            ob[(size_t)c0 * HW + r]           = xb[(size_t)c0 * HW + r]           + acc[mi][nj][0] + bv0;
            ob[(size_t)(c0 + 1) * HW + r]     = xb[(size_t)(c0 + 1) * HW + r]     + acc[mi][nj][1] + bv1;
            ob[(size_t)c0 * HW + r + 8]       = xb[(size_t)c0 * HW + r + 8]       + acc[mi][nj][2] + bv0;
            ob[(size_t)(c0 + 1) * HW + r + 8] = xb[(size_t)(c0 + 1) * HW + r + 8] + acc[mi][nj][3] + bv1;
        }
    }
}

// ------------------------------ launch ---------------------------------------
extern "C" void kernel_launch(void* const* d_in, const int* in_sizes, int n_in,
                              void* d_out, int out_size) {
    const float* x  = (const float*)d_in[0];
    const float* nw = (const float*)d_in[1];
    const float* nb = (const float*)d_in[2];
    const float* wq = (const float*)d_in[3];
    const float* bq = (const float*)d_in[4];
    const float* wk = (const float*)d_in[5];
    const float* bk = (const float*)d_in[6];
    const float* wv = (const float*)d_in[7];
    const float* bv = (const float*)d_in[8];
    const float* wp = (const float*)d_in[9];
    const float* bp = (const float*)d_in[10];
    float* out = (float*)d_out;

    groupnorm_kernel<<<BATCH * NGRP, 256>>>(x, nw, nb);

    dim3 gqkv(HW / 128, CCH / 128, BATCH);      // 32 x 4 x 2
    qkv_mma_kernel<<<gqkv, 256>>>(wq, bq, 0);
    qkv_mma_kernel<<<gqkv, 256>>>(wk, bk, 1);
    qkv_mma_kernel<<<gqkv, 256>>>(wv, bv, 2);

    dim3 gsc(HW / 128, HW / 128, BATCH);        // 32 x 32 x 2
    scores_mma_kernel<<<gsc, 256>>>();

    softmax_kernel<<<BATCH * HW, 256>>>();

    o_mma_kernel<<<gqkv, 256>>>();

    proj_mma_kernel<<<gqkv, 256>>>(wp, bp, x, out);
}

// round 7
// speedup vs baseline: 3.7316x; 1.1807x over previous
#include <cuda_runtime.h>
#include <math.h>
#include <float.h>
#include <stdint.h>

#define BATCH 2
#define CCH   512
#define HW    4096
#define NGRP  32
#define CPG   16
#define GRPELEM (CPG * HW)   // 65536

#define PMK 20    // padded row len for [row][k16] tiles (128 x 16)
#define PKM 136   // padded row len for [k16][col] tiles (16 x 128)

// per-stage float counts
#define QKV_STG (16 * PKM + 128 * PMK)   // A(KM) + B(MK)
#define SC_STG  (2 * 128 * PMK)          // A(MK) + B(MK)
#define O_STG   (2 * 16 * PKM)           // A(KM) + B(KM)
#define QKV_DYN (3 * QKV_STG * 4)
#define SC_DYN  (3 * SC_STG * 4)
#define O_DYN   (3 * O_STG * 4)

// ---------------- scratch (static device globals; no allocation) -------------
__device__ float g_hn  [(size_t)BATCH * CCH * HW];  // normed, [b][c][n]
__device__ float g_q   [(size_t)BATCH * HW * CCH];  // [b][i][c]
__device__ float g_k   [(size_t)BATCH * HW * CCH];  // [b][j][c]
__device__ float g_v   [(size_t)BATCH * HW * CCH];  // [b][i][c] (later scaled by 1/Z_i)
__device__ float g_s   [(size_t)BATCH * HW * HW];   // E[i][j] = exp(scale*S)
__device__ float g_o   [(size_t)BATCH * HW * CCH];  // attn out [b][j][c]
__device__ float g_zinv[(size_t)BATCH * HW];        // 1 / row sums of E

// ------------------------------ helpers --------------------------------------
__device__ __forceinline__ void mma8(float* d, const unsigned* a, const unsigned* b) {
    asm volatile(
        "mma.sync.aligned.m16n8k8.row.col.f32.tf32.tf32.f32 "
        "{%0,%1,%2,%3}, {%4,%5,%6,%7}, {%8,%9}, {%0,%1,%2,%3};\n"
        : "+f"(d[0]), "+f"(d[1]), "+f"(d[2]), "+f"(d[3])
        : "r"(a[0]), "r"(a[1]), "r"(a[2]), "r"(a[3]), "r"(b[0]), "r"(b[1]));
}
__device__ __forceinline__ unsigned sptr(const void* p) {
    return (unsigned)__cvta_generic_to_shared(p);
}
#define CPA16(dst, src) asm volatile("cp.async.ca.shared.global [%0], [%1], 16;\n" :: "r"(dst), "l"(src))
#define CPCOMMIT()      asm volatile("cp.async.commit_group;\n")
#define CPWAIT1()       asm volatile("cp.async.wait_group 1;\n" ::: "memory")
__device__ __forceinline__ unsigned fu(float f) { return __float_as_uint(f); }

// ---------------------------- GroupNorm --------------------------------------
__global__ void groupnorm_kernel(const float* __restrict__ x,
                                 const float* __restrict__ gw,
                                 const float* __restrict__ gb) {
    int b = blockIdx.x >> 5;
    int g = blockIdx.x & 31;
    const float4* xp = (const float4*)(x    + ((size_t)b * CCH + g * CPG) * HW);
    float4*       op = (float4*)      (g_hn + ((size_t)b * CCH + g * CPG) * HW);
    int tid = threadIdx.x;

    float s = 0.f, ss = 0.f;
    for (int i = tid; i < GRPELEM / 4; i += 256) {
        float4 v = xp[i];
        s  += v.x + v.y + v.z + v.w;
        ss += v.x * v.x + v.y * v.y + v.z * v.z + v.w * v.w;
    }
    __shared__ float shs[8], shss[8];
    #pragma unroll
    for (int o = 16; o; o >>= 1) {
        s  += __shfl_xor_sync(0xffffffffu, s,  o);
        ss += __shfl_xor_sync(0xffffffffu, ss, o);
    }
    if ((tid & 31) == 0) { shs[tid >> 5] = s; shss[tid >> 5] = ss; }
    __syncthreads();
    __shared__ float sm, sr;
    if (tid == 0) {
        float S = 0.f, SS = 0.f;
        #pragma unroll
        for (int i = 0; i < 8; i++) { S += shs[i]; SS += shss[i]; }
        float mean = S / (float)GRPELEM;
        float var  = SS / (float)GRPELEM - mean * mean;
        sm = mean;
        sr = rsqrtf(var + 1e-6f);
    }
    __syncthreads();
    float mean = sm, rstd = sr;
    for (int i = tid; i < GRPELEM / 4; i += 256) {
        int cl = i >> 10;
        float sc = gw[g * CPG + cl] * rstd;
        float sh = gb[g * CPG + cl] - mean * sc;
        float4 v = xp[i];
        v.x = v.x * sc + sh; v.y = v.y * sc + sh;
        v.z = v.z * sc + sh; v.w = v.w * sc + sh;
        op[i] = v;
    }
}

// ---- frag loaders -----------------------------------------------------------
// KM tile [k16][PKM], fragment for row-major A of m16n8k8 (k = tile row)
#define LOAD_AF_KM(af, Ab, kk, wm) do {                                        \
    _Pragma("unroll")                                                          \
    for (int mi = 0; mi < 4; mi++) {                                           \
        int mb = (wm) + mi * 16 + g;                                           \
        (af)[mi][0] = fu((Ab)[((kk) + tig) * PKM + mb]);                       \
        (af)[mi][1] = fu((Ab)[((kk) + tig) * PKM + mb + 8]);                   \
        (af)[mi][2] = fu((Ab)[((kk) + tig + 4) * PKM + mb]);                   \
        (af)[mi][3] = fu((Ab)[((kk) + tig + 4) * PKM + mb + 8]);               \
    } } while (0)
// MK tile [row][PMK]
#define LOAD_AF_MK(af, Ab, kk, wm) do {                                        \
    _Pragma("unroll")                                                          \
    for (int mi = 0; mi < 4; mi++) {                                           \
        int mb = (wm) + mi * 16 + g;                                           \
        (af)[mi][0] = fu((Ab)[mb * PMK + (kk) + tig]);                         \
        (af)[mi][1] = fu((Ab)[(mb + 8) * PMK + (kk) + tig]);                   \
        (af)[mi][2] = fu((Ab)[mb * PMK + (kk) + tig + 4]);                     \
        (af)[mi][3] = fu((Ab)[(mb + 8) * PMK + (kk) + tig + 4]);               \
    } } while (0)
#define LOAD_BF_MK(bf, Bb, kk, wn) do {                                        \
    _Pragma("unroll")                                                          \
    for (int nj = 0; nj < 4; nj++) {                                           \
        int nb = (wn) + nj * 8 + g;                                            \
        (bf)[nj][0] = fu((Bb)[nb * PMK + (kk) + tig]);                         \
        (bf)[nj][1] = fu((Bb)[nb * PMK + (kk) + tig + 4]);                     \
    } } while (0)
#define LOAD_BF_KM(bf, Bb, kk, wn) do {                                        \
    _Pragma("unroll")                                                          \
    for (int nj = 0; nj < 4; nj++) {                                           \
        int nb = (wn) + nj * 8 + g;                                            \
        (bf)[nj][0] = fu((Bb)[((kk) + tig) * PKM + nb]);                       \
        (bf)[nj][1] = fu((Bb)[((kk) + tig + 4) * PKM + nb]);                   \
    } } while (0)
#define MMA_ALL(acc, af, bf) do {                                              \
    _Pragma("unroll")                                                          \
    for (int mi = 0; mi < 4; mi++)                                             \
        _Pragma("unroll")                                                      \
        for (int nj = 0; nj < 4; nj++) mma8((acc)[mi][nj], (af)[mi], (bf)[nj]);\
    } while (0)

// -------- QKV GEMM (merged): C[m,n] = sum_k A[k,m] * W[n,k] + bias[n] --------
__global__ __launch_bounds__(256, 2)
void qkv_mma_kernel(const float* __restrict__ wq, const float* __restrict__ bq,
                    const float* __restrict__ wk, const float* __restrict__ bk,
                    const float* __restrict__ wv, const float* __restrict__ bv) {
    extern __shared__ float smem[];
    int b = blockIdx.z;
    int which = blockIdx.y >> 2;
    int n0 = (blockIdx.y & 3) * 128, m0 = blockIdx.x * 128;
    const float* Wt   = which == 0 ? wq : which == 1 ? wk : wv;
    const float* bias = which == 0 ? bq : which == 1 ? bk : bv;
    float* Cp = (which == 0 ? g_q : which == 1 ? g_k : g_v) + (size_t)b * HW * CCH;
    const float* Ag = g_hn + (size_t)b * CCH * HW + m0;
    int tid = threadIdx.x;
    int lane = tid & 31, warp = tid >> 5;
    int g = lane >> 2, tig = lane & 3;
    int wm = (warp >> 2) * 64, wn = (warp & 3) * 32;
    // A loader: 16 rows x 128 floats; row = (tid>>5)+8rr, chunk (tid&31)*4
    int arow = tid >> 5, acol = (tid & 31) << 2;
    // B loader: 128 rows x 16 floats; row = (tid>>2)+64rr, chunk (tid&3)*4
    int brow = tid >> 2, bcol = (tid & 3) << 2;

    float acc[4][4][4];
    #pragma unroll
    for (int i = 0; i < 4; i++)
        #pragma unroll
        for (int j = 0; j < 4; j++)
            #pragma unroll
            for (int t = 0; t < 4; t++) acc[i][j][t] = 0.f;

    const int NT = CCH / 16;
    #pragma unroll
    for (int s = 0; s < 2; s++) {
        float* As = smem + s * QKV_STG;
        float* Bs = As + 16 * PKM;
        #pragma unroll
        for (int rr = 0; rr < 2; rr++) {
            int r = arow + rr * 8;
            CPA16(sptr(&As[r * PKM + acol]), Ag + (size_t)(s * 16 + r) * HW + acol);
        }
        #pragma unroll
        for (int rr = 0; rr < 2; rr++) {
            int r = brow + rr * 64;
            CPA16(sptr(&Bs[r * PMK + bcol]), Wt + (size_t)(n0 + r) * CCH + s * 16 + bcol);
        }
        CPCOMMIT();
    }
    for (int kt = 0; kt < NT; kt++) {
        CPWAIT1();
        __syncthreads();
        const float* Ab = smem + (kt % 3) * QKV_STG;
        const float* Bb = Ab + 16 * PKM;
        unsigned af[2][4][4], bf[2][4][2];
        LOAD_AF_KM(af[0], Ab, 0, wm);
        LOAD_BF_MK(bf[0], Bb, 0, wn);
        LOAD_AF_KM(af[1], Ab, 8, wm);
        LOAD_BF_MK(bf[1], Bb, 8, wn);
        MMA_ALL(acc, af[0], bf[0]);
        MMA_ALL(acc, af[1], bf[1]);
        int nk = kt + 2;
        if (nk < NT) {
            float* As = smem + (nk % 3) * QKV_STG;
            float* Bs = As + 16 * PKM;
            #pragma unroll
            for (int rr = 0; rr < 2; rr++) {
                int r = arow + rr * 8;
                CPA16(sptr(&As[r * PKM + acol]), Ag + (size_t)(nk * 16 + r) * HW + acol);
            }
            #pragma unroll
            for (int rr = 0; rr < 2; rr++) {
                int r = brow + rr * 64;
                CPA16(sptr(&Bs[r * PMK + bcol]), Wt + (size_t)(n0 + r) * CCH + nk * 16 + bcol);
            }
        }
        CPCOMMIT();
    }
    #pragma unroll
    for (int mi = 0; mi < 4; mi++)
        #pragma unroll
        for (int nj = 0; nj < 4; nj++) {
            int r = m0 + wm + mi * 16 + g;
            int c = n0 + wn + nj * 8 + 2 * tig;
            float bv0 = bias[c], bv1 = bias[c + 1];
            *(float2*)&Cp[(size_t)r * CCH + c] =
                make_float2(acc[mi][nj][0] + bv0, acc[mi][nj][1] + bv1);
            *(float2*)&Cp[(size_t)(r + 8) * CCH + c] =
                make_float2(acc[mi][nj][2] + bv0, acc[mi][nj][3] + bv1);
        }
}

// -------- Scores: E[i,j] = exp(scale * sum_c Q[i,c]*K[j,c]) ------------------
__global__ __launch_bounds__(256, 2)
void scores_mma_kernel() {
    extern __shared__ float smem[];
    int b = blockIdx.z;
    const float* Ag = g_q + (size_t)b * HW * CCH + (size_t)blockIdx.x * 128 * CCH;
    const float* Bg = g_k + (size_t)b * HW * CCH + (size_t)blockIdx.y * 128 * CCH;
    int tid = threadIdx.x;
    int lane = tid & 31, warp = tid >> 5;
    int g = lane >> 2, tig = lane & 3;
    int wm = (warp >> 2) * 64, wn = (warp & 3) * 32;
    int brow = tid >> 2, bcol = (tid & 3) << 2;

    float acc[4][4][4];
    #pragma unroll
    for (int i = 0; i < 4; i++)
        #pragma unroll
        for (int j = 0; j < 4; j++)
            #pragma unroll
            for (int t = 0; t < 4; t++) acc[i][j][t] = 0.f;

    const int NT = CCH / 16;
    #pragma unroll
    for (int s = 0; s < 2; s++) {
        float* As = smem + s * SC_STG;
        float* Bs = As + 128 * PMK;
        #pragma unroll
        for (int rr = 0; rr < 2; rr++) {
            int r = brow + rr * 64;
            CPA16(sptr(&As[r * PMK + bcol]), Ag + (size_t)r * CCH + s * 16 + bcol);
            CPA16(sptr(&Bs[r * PMK + bcol]), Bg + (size_t)r * CCH + s * 16 + bcol);
        }
        CPCOMMIT();
    }
    for (int kt = 0; kt < NT; kt++) {
        CPWAIT1();
        __syncthreads();
        const float* Ab = smem + (kt % 3) * SC_STG;
        const float* Bb = Ab + 128 * PMK;
        unsigned af[2][4][4], bf[2][4][2];
        LOAD_AF_MK(af[0], Ab, 0, wm);
        LOAD_BF_MK(bf[0], Bb, 0, wn);
        LOAD_AF_MK(af[1], Ab, 8, wm);
        LOAD_BF_MK(bf[1], Bb, 8, wn);
        MMA_ALL(acc, af[0], bf[0]);
        MMA_ALL(acc, af[1], bf[1]);
        int nk = kt + 2;
        if (nk < NT) {
            float* As = smem + (nk % 3) * SC_STG;
            float* Bs = As + 128 * PMK;
            #pragma unroll
            for (int rr = 0; rr < 2; rr++) {
                int r = brow + rr * 64;
                CPA16(sptr(&As[r * PMK + bcol]), Ag + (size_t)r * CCH + nk * 16 + bcol);
                CPA16(sptr(&Bs[r * PMK + bcol]), Bg + (size_t)r * CCH + nk * 16 + bcol);
            }
        }
        CPCOMMIT();
    }
    const float scale = 0.04419417382415922f;   // 512^-0.5
    float* Cp = g_s + (size_t)b * HW * HW;
    int m0 = blockIdx.x * 128, n0 = blockIdx.y * 128;
    #pragma unroll
    for (int mi = 0; mi < 4; mi++)
        #pragma unroll
        for (int nj = 0; nj < 4; nj++) {
            int r = m0 + wm + mi * 16 + g;
            int c = n0 + wn + nj * 8 + 2 * tig;
            *(float2*)&Cp[(size_t)r * HW + c] =
                make_float2(__expf(acc[mi][nj][0] * scale), __expf(acc[mi][nj][1] * scale));
            *(float2*)&Cp[(size_t)(r + 8) * HW + c] =
                make_float2(__expf(acc[mi][nj][2] * scale), __expf(acc[mi][nj][3] * scale));
        }
}

// ------- row sums of E: g_zinv[b][i] = 1 / sum_j E[i,j] ----------------------
__global__ void rowsum_kernel() {
    const float4* row = (const float4*)(g_s + ((size_t)blockIdx.y * HW + blockIdx.x) * HW);
    int tid = threadIdx.x;
    float s = 0.f;
    #pragma unroll
    for (int t = 0; t < 4; t++) {
        float4 v = row[tid + t * 256];
        s += (v.x + v.y) + (v.z + v.w);
    }
    __shared__ float red[8];
    #pragma unroll
    for (int o = 16; o; o >>= 1) s += __shfl_xor_sync(0xffffffffu, s, o);
    if ((tid & 31) == 0) red[tid >> 5] = s;
    __syncthreads();
    if (tid == 0) {
        float t = 0.f;
        #pragma unroll
        for (int i = 0; i < 8; i++) t += red[i];
        g_zinv[(size_t)blockIdx.y * HW + blockIdx.x] = 1.f / t;
    }
}

// ------- fold 1/Z into V rows: g_v[b][i][c] *= g_zinv[b][i] ------------------
__global__ void vscale_kernel() {
    size_t idx = (size_t)blockIdx.x * 256 + threadIdx.x;   // float4 index
    int b = (int)(idx / ((size_t)HW * CCH / 4));
    size_t rem = idx - (size_t)b * (HW * CCH / 4);
    int i = (int)(rem / (CCH / 4));
    float z = g_zinv[(size_t)b * HW + i];
    float4 v = ((float4*)g_v)[idx];
    v.x *= z; v.y *= z; v.z *= z; v.w *= z;
    ((float4*)g_v)[idx] = v;
}

// ------ O GEMM: O[j,c] = sum_i E[i,j] * Vhat[i,c] ----------------------------
__global__ __launch_bounds__(256, 2)
void o_mma_kernel() {
    extern __shared__ float smem[];
    int b = blockIdx.z;
    const float* Ag = g_s + (size_t)b * HW * HW + blockIdx.x * 128;
    const float* Bg = g_v + (size_t)b * HW * CCH + blockIdx.y * 128;
    int tid = threadIdx.x;
    int lane = tid & 31, warp = tid >> 5;
    int g = lane >> 2, tig = lane & 3;
    int wm = (warp >> 2) * 64, wn = (warp & 3) * 32;
    int arow = tid >> 5, acol = (tid & 31) << 2;

    float acc[4][4][4];
    #pragma unroll
    for (int i = 0; i < 4; i++)
        #pragma unroll
        for (int j = 0; j < 4; j++)
            #pragma unroll
            for (int t = 0; t < 4; t++) acc[i][j][t] = 0.f;

    const int NT = HW / 16;
    #pragma unroll
    for (int s = 0; s < 2; s++) {
        float* As = smem + s * O_STG;
        float* Bs = As + 16 * PKM;
        #pragma unroll
        for (int rr = 0; rr < 2; rr++) {
            int r = arow + rr * 8;
            CPA16(sptr(&As[r * PKM + acol]), Ag + (size_t)(s * 16 + r) * HW + acol);
            CPA16(sptr(&Bs[r * PKM + acol]), Bg + (size_t)(s * 16 + r) * CCH + acol);
        }
        CPCOMMIT();
    }
    for (int kt = 0; kt < NT; kt++) {
        CPWAIT1();
        __syncthreads();
        const float* Ab = smem + (kt % 3) * O_STG;
        const float* Bb = Ab + 16 * PKM;
        unsigned af[2][4][4], bf[2][4][2];
        LOAD_AF_KM(af[0], Ab, 0, wm);
        LOAD_BF_KM(bf[0], Bb, 0, wn);
        LOAD_AF_KM(af[1], Ab, 8, wm);
        LOAD_BF_KM(bf[1], Bb, 8, wn);
        MMA_ALL(acc, af[0], bf[0]);
        MMA_ALL(acc, af[1], bf[1]);
        int nk = kt + 2;
        if (nk < NT) {
            float* As = smem + (nk % 3) * O_STG;
            float* Bs = As + 16 * PKM;
            #pragma unroll
            for (int rr = 0; rr < 2; rr++) {
                int r = arow + rr * 8;
                CPA16(sptr(&As[r * PKM + acol]), Ag + (size_t)(nk * 16 + r) * HW + acol);
                CPA16(sptr(&Bs[r * PKM + acol]), Bg + (size_t)(nk * 16 + r) * CCH + acol);
            }
        }
        CPCOMMIT();
    }
    float* Cp = g_o + (size_t)b * HW * CCH;
    int m0 = blockIdx.x * 128, n0 = blockIdx.y * 128;
    #pragma unroll
    for (int mi = 0; mi < 4; mi++)
        #pragma unroll
        for (int nj = 0; nj < 4; nj++) {
            int r = m0 + wm + mi * 16 + g;
            int c = n0 + wn + nj * 8 + 2 * tig;
            *(float2*)&Cp[(size_t)r * CCH + c] =
                make_float2(acc[mi][nj][0], acc[mi][nj][1]);
            *(float2*)&Cp[(size_t)(r + 8) * CCH + c] =
                make_float2(acc[mi][nj][2], acc[mi][nj][3]);
        }
}

// ------ Proj+residual: out[o,m] = x[o,m] + sum_c O[m,c]Wp[o,c]+bp[o] ---------
__global__ __launch_bounds__(256, 2)
void proj_mma_kernel(const float* __restrict__ Wp, const float* __restrict__ bp,
                     const float* __restrict__ x, float* __restrict__ out) {
    extern __shared__ float smem[];
    int b = blockIdx.z;
    const float* Ag = g_o + (size_t)b * HW * CCH + (size_t)blockIdx.x * 128 * CCH;
    const float* xb = x   + (size_t)b * CCH * HW;
    float* ob = out + (size_t)b * CCH * HW;
    int n0 = blockIdx.y * 128, m0 = blockIdx.x * 128;
    int tid = threadIdx.x;
    int lane = tid & 31, warp = tid >> 5;
    int g = lane >> 2, tig = lane & 3;
    int wm = (warp >> 2) * 64, wn = (warp & 3) * 32;
    int brow = tid >> 2, bcol = (tid & 3) << 2;

    float acc[4][4][4];
    #pragma unroll
    for (int i = 0; i < 4; i++)
        #pragma unroll
        for (int j = 0; j < 4; j++)
            #pragma unroll
            for (int t = 0; t < 4; t++) acc[i][j][t] = 0.f;

    const int NT = CCH / 16;
    #pragma unroll
    for (int s = 0; s < 2; s++) {
        float* As = smem + s * SC_STG;
        float* Bs = As + 128 * PMK;
        #pragma unroll
        for (int rr = 0; rr < 2; rr++) {
            int r = brow + rr * 64;
            CPA16(sptr(&As[r * PMK + bcol]), Ag + (size_t)r * CCH + s * 16 + bcol);
            CPA16(sptr(&Bs[r * PMK + bcol]), Wp + (size_t)(n0 + r) * CCH + s * 16 + bcol);
        }
        CPCOMMIT();
    }
    for (int kt = 0; kt < NT; kt++) {
        CPWAIT1();
        __syncthreads();
        const float* Ab = smem + (kt % 3) * SC_STG;
        const float* Bb = Ab + 128 * PMK;
        unsigned af[2][4][4], bf[2][4][2];
        LOAD_AF_MK(af[0], Ab, 0, wm);
        LOAD_BF_MK(bf[0], Bb, 0, wn);
        LOAD_AF_MK(af[1], Ab, 8, wm);
        LOAD_BF_MK(bf[1], Bb, 8, wn);
        MMA_ALL(acc, af[0], bf[0]);
        MMA_ALL(acc, af[1], bf[1]);
        int nk = kt + 2;
        if (nk < NT) {
            float* As = smem + (nk % 3) * SC_STG;
            float* Bs = As + 128 * PMK;
            #pragma unroll
            for (int rr = 0; rr < 2; rr++) {
                int r = brow + rr * 64;
                CPA16(sptr(&As[r * PMK + bcol]), Ag + (size_t)r * CCH + nk * 16 + bcol);
                CPA16(sptr(&Bs[r * PMK + bcol]), Wp + (size_t)(n0 + r) * CCH + nk * 16 + bcol);
            }
        }
        CPCOMMIT();
    }
    #pragma unroll
    for (int nj = 0; nj < 4; nj++) {
        int c0 = n0 + wn + nj * 8 + 2 * tig;
        float bv0 = bp[c0], bv1 = bp[c0 + 1];
        #pragma unroll
        for (int mi = 0; mi < 4; mi++) {
            int r = m0 + wm + mi * 16 + g;
            ob[(size_t)c0 * HW + r]           = xb[(size_t)c0 * HW + r]           + acc[mi][nj][0] + bv0;
            ob[(size_t)(c0 + 1) * HW + r]     = xb[(size_t)(c0 + 1) * HW + r]     + acc[mi][nj][1] + bv1;
            ob[(size_t)c0 * HW + r + 8]       = xb[(size_t)c0 * HW + r + 8]       + acc[mi][nj][2] + bv0;
            ob[(size_t)(c0 + 1) * HW + r + 8] = xb[(size_t)(c0 + 1) * HW + r + 8] + acc[mi][nj][3] + bv1;
        }
    }
}

// ------------------------------ launch ---------------------------------------
extern "C" void kernel_launch(void* const* d_in, const int* in_sizes, int n_in,
                              void* d_out, int out_size) {
    const float* x  = (const float*)d_in[0];
    const float* nw = (const float*)d_in[1];
    const float* nb = (const float*)d_in[2];
    const float* wq = (const float*)d_in[3];
    const float* bq = (const float*)d_in[4];
    const float* wk = (const float*)d_in[5];
    const float* bk = (const float*)d_in[6];
    const float* wv = (const float*)d_in[7];
    const float* bv = (const float*)d_in[8];
    const float* wp = (const float*)d_in[9];
    const float* bp = (const float*)d_in[10];
    float* out = (float*)d_out;

    static int attr_done = 0;
    if (!attr_done) {
        cudaFuncSetAttribute(qkv_mma_kernel,
                             cudaFuncAttributeMaxDynamicSharedMemorySize, QKV_DYN);
        cudaFuncSetAttribute(scores_mma_kernel,
                             cudaFuncAttributeMaxDynamicSharedMemorySize, SC_DYN);
        cudaFuncSetAttribute(o_mma_kernel,
                             cudaFuncAttributeMaxDynamicSharedMemorySize, O_DYN);
        cudaFuncSetAttribute(proj_mma_kernel,
                             cudaFuncAttributeMaxDynamicSharedMemorySize, SC_DYN);
        attr_done = 1;
    }

    groupnorm_kernel<<<BATCH * NGRP, 256>>>(x, nw, nb);

    dim3 gqkv(HW / 128, 3 * CCH / 128, BATCH);  // 32 x 12 x 2
    qkv_mma_kernel<<<gqkv, 256, QKV_DYN>>>(wq, bq, wk, bk, wv, bv);

    dim3 gsc(HW / 128, HW / 128, BATCH);        // 32 x 32 x 2
    scores_mma_kernel<<<gsc, 256, SC_DYN>>>();

    dim3 grs(HW, BATCH);
    rowsum_kernel<<<grs, 256>>>();
    vscale_kernel<<<(BATCH * HW * CCH) / (4 * 256), 256>>>();

    dim3 go(HW / 128, CCH / 128, BATCH);        // 32 x 4 x 2
    o_mma_kernel<<<go, 256, O_DYN>>>();

    proj_mma_kernel<<<go, 256, SC_DYN>>>(wp, bp, x, out);
}

// round 8
// speedup vs baseline: 3.9938x; 1.0703x over previous
#include <cuda_runtime.h>
#include <cuda_bf16.h>
#include <math.h>
#include <float.h>
#include <stdint.h>

#define BATCH 2
#define CCH   512
#define HW    4096
#define NGRP  32
#define CPG   16
#define GRPELEM (CPG * HW)   // 65536

#define PMK 20    // padded row len for [row][k16] fp32 tiles (128 x 16)
#define PKM 136   // padded row len for [k16][col] fp32 tiles (16 x 128)

// per-stage float counts (tf32 kernels)
#define QKV_STG (16 * PKM + 128 * PMK)
#define SC_STG  (2 * 128 * PMK)
#define QKV_DYN (3 * QKV_STG * 4)
#define SC_DYN  (3 * SC_STG * 4)

// bf16 O GEMM geometry: k-chunk 32, rows padded to 20 words (40 bf16, 80 B)
#define OROWW 20
#define O_STG_WORDS (2 * 128 * OROWW)      // A + B per stage, in 32-bit words
#define O_STG_BYTES (O_STG_WORDS * 4)      // 20480 B
#define O_DYN_B (3 * O_STG_BYTES)          // 61440 B

// ---------------- scratch (static device globals; no allocation) -------------
__device__ float         g_hn  [(size_t)BATCH * CCH * HW];  // normed [b][c][n]
__device__ float         g_q   [(size_t)BATCH * HW * CCH];  // [b][i][c]
__device__ float         g_k   [(size_t)BATCH * HW * CCH];  // [b][j][c]
__device__ float         g_vt  [(size_t)BATCH * CCH * HW];  // [b][c][i] fp32
__device__ __nv_bfloat16 g_vb  [(size_t)BATCH * CCH * HW];  // [b][c][i] bf16 * 1/Z_i
__device__ __nv_bfloat16 g_s   [(size_t)BATCH * HW * HW];   // E'[j][i] = exp(scale*S^T)
__device__ float         g_o   [(size_t)BATCH * HW * CCH];  // attn out [b][j][c]
__device__ float         g_zp  [(size_t)BATCH * 8 * HW];    // partial column sums
__device__ float         g_z   [(size_t)BATCH * HW];        // 1/Z_i

// ------------------------------ helpers --------------------------------------
__device__ __forceinline__ void mma8(float* d, const unsigned* a, const unsigned* b) {
    asm volatile(
        "mma.sync.aligned.m16n8k8.row.col.f32.tf32.tf32.f32 "
        "{%0,%1,%2,%3}, {%4,%5,%6,%7}, {%8,%9}, {%0,%1,%2,%3};\n"
        : "+f"(d[0]), "+f"(d[1]), "+f"(d[2]), "+f"(d[3])
        : "r"(a[0]), "r"(a[1]), "r"(a[2]), "r"(a[3]), "r"(b[0]), "r"(b[1]));
}
__device__ __forceinline__ void mma16(float* d, const unsigned* a, const unsigned* b) {
    asm volatile(
        "mma.sync.aligned.m16n8k16.row.col.f32.bf16.bf16.f32 "
        "{%0,%1,%2,%3}, {%4,%5,%6,%7}, {%8,%9}, {%0,%1,%2,%3};\n"
        : "+f"(d[0]), "+f"(d[1]), "+f"(d[2]), "+f"(d[3])
        : "r"(a[0]), "r"(a[1]), "r"(a[2]), "r"(a[3]), "r"(b[0]), "r"(b[1]));
}
__device__ __forceinline__ unsigned sptr(const void* p) {
    return (unsigned)__cvta_generic_to_shared(p);
}
#define CPA16(dst, src) asm volatile("cp.async.ca.shared.global [%0], [%1], 16;\n" :: "r"(dst), "l"(src))
#define CPCOMMIT()      asm volatile("cp.async.commit_group;\n")
#define CPWAIT1()       asm volatile("cp.async.wait_group 1;\n" ::: "memory")
__device__ __forceinline__ unsigned fu(float f) { return __float_as_uint(f); }

// ---------------------------- GroupNorm --------------------------------------
__global__ void groupnorm_kernel(const float* __restrict__ x,
                                 const float* __restrict__ gw,
                                 const float* __restrict__ gb) {
    int b = blockIdx.x >> 5;
    int g = blockIdx.x & 31;
    const float4* xp = (const float4*)(x    + ((size_t)b * CCH + g * CPG) * HW);
    float4*       op = (float4*)      (g_hn + ((size_t)b * CCH + g * CPG) * HW);
    int tid = threadIdx.x;

    float s = 0.f, ss = 0.f;
    for (int i = tid; i < GRPELEM / 4; i += 256) {
        float4 v = xp[i];
        s  += v.x + v.y + v.z + v.w;
        ss += v.x * v.x + v.y * v.y + v.z * v.z + v.w * v.w;
    }
    __shared__ float shs[8], shss[8];
    #pragma unroll
    for (int o = 16; o; o >>= 1) {
        s  += __shfl_xor_sync(0xffffffffu, s,  o);
        ss += __shfl_xor_sync(0xffffffffu, ss, o);
    }
    if ((tid & 31) == 0) { shs[tid >> 5] = s; shss[tid >> 5] = ss; }
    __syncthreads();
    __shared__ float sm, sr;
    if (tid == 0) {
        float S = 0.f, SS = 0.f;
        #pragma unroll
        for (int i = 0; i < 8; i++) { S += shs[i]; SS += shss[i]; }
        float mean = S / (float)GRPELEM;
        float var  = SS / (float)GRPELEM - mean * mean;
        sm = mean;
        sr = rsqrtf(var + 1e-6f);
    }
    __syncthreads();
    float mean = sm, rstd = sr;
    for (int i = tid; i < GRPELEM / 4; i += 256) {
        int cl = i >> 10;
        float sc = gw[g * CPG + cl] * rstd;
        float sh = gb[g * CPG + cl] - mean * sc;
        float4 v = xp[i];
        v.x = v.x * sc + sh; v.y = v.y * sc + sh;
        v.z = v.z * sc + sh; v.w = v.w * sc + sh;
        op[i] = v;
    }
}

// ---- frag loaders (fp32/tf32 tiles) -----------------------------------------
#define LOAD_AF_KM(af, Ab, kk, wm) do {                                        \
    _Pragma("unroll")                                                          \
    for (int mi = 0; mi < 4; mi++) {                                           \
        int mb = (wm) + mi * 16 + g;                                           \
        (af)[mi][0] = fu((Ab)[((kk) + tig) * PKM + mb]);                       \
        (af)[mi][1] = fu((Ab)[((kk) + tig) * PKM + mb + 8]);                   \
        (af)[mi][2] = fu((Ab)[((kk) + tig + 4) * PKM + mb]);                   \
        (af)[mi][3] = fu((Ab)[((kk) + tig + 4) * PKM + mb + 8]);               \
    } } while (0)
#define LOAD_AF_MK(af, Ab, kk, wm) do {                                        \
    _Pragma("unroll")                                                          \
    for (int mi = 0; mi < 4; mi++) {                                           \
        int mb = (wm) + mi * 16 + g;                                           \
        (af)[mi][0] = fu((Ab)[mb * PMK + (kk) + tig]);                         \
        (af)[mi][1] = fu((Ab)[(mb + 8) * PMK + (kk) + tig]);                   \
        (af)[mi][2] = fu((Ab)[mb * PMK + (kk) + tig + 4]);                     \
        (af)[mi][3] = fu((Ab)[(mb + 8) * PMK + (kk) + tig + 4]);               \
    } } while (0)
#define LOAD_BF_MK(bf, Bb, kk, wn) do {                                        \
    _Pragma("unroll")                                                          \
    for (int nj = 0; nj < 4; nj++) {                                           \
        int nb = (wn) + nj * 8 + g;                                            \
        (bf)[nj][0] = fu((Bb)[nb * PMK + (kk) + tig]);                         \
        (bf)[nj][1] = fu((Bb)[nb * PMK + (kk) + tig + 4]);                     \
    } } while (0)
#define MMA_ALL8(acc, af, bf) do {                                             \
    _Pragma("unroll")                                                          \
    for (int mi = 0; mi < 4; mi++)                                             \
        _Pragma("unroll")                                                      \
        for (int nj = 0; nj < 4; nj++) mma8((acc)[mi][nj], (af)[mi], (bf)[nj]);\
    } while (0)

// -------- QKV GEMM (merged): C[m,n] = sum_k A[k,m] * W[n,k] + bias[n] --------
// which 0 -> g_q [i][c], 1 -> g_k [j][c], 2 -> g_vt [c][i] (transposed)
__global__ __launch_bounds__(256, 2)
void qkv_mma_kernel(const float* __restrict__ wq, const float* __restrict__ bq,
                    const float* __restrict__ wk, const float* __restrict__ bk,
                    const float* __restrict__ wv, const float* __restrict__ bv) {
    extern __shared__ float smem[];
    int b = blockIdx.z;
    int which = blockIdx.y >> 2;
    int n0 = (blockIdx.y & 3) * 128, m0 = blockIdx.x * 128;
    const float* Wt   = which == 0 ? wq : which == 1 ? wk : wv;
    const float* bias = which == 0 ? bq : which == 1 ? bk : bv;
    const float* Ag = g_hn + (size_t)b * CCH * HW + m0;
    int tid = threadIdx.x;
    int lane = tid & 31, warp = tid >> 5;
    int g = lane >> 2, tig = lane & 3;
    int wm = (warp >> 2) * 64, wn = (warp & 3) * 32;
    int arow = tid >> 5, acol = (tid & 31) << 2;
    int brow = tid >> 2, bcol = (tid & 3) << 2;

    float acc[4][4][4];
    #pragma unroll
    for (int i = 0; i < 4; i++)
        #pragma unroll
        for (int j = 0; j < 4; j++)
            #pragma unroll
            for (int t = 0; t < 4; t++) acc[i][j][t] = 0.f;

    const int NT = CCH / 16;
    #pragma unroll
    for (int s = 0; s < 2; s++) {
        float* As = smem + s * QKV_STG;
        float* Bs = As + 16 * PKM;
        #pragma unroll
        for (int rr = 0; rr < 2; rr++) {
            int r = arow + rr * 8;
            CPA16(sptr(&As[r * PKM + acol]), Ag + (size_t)(s * 16 + r) * HW + acol);
        }
        #pragma unroll
        for (int rr = 0; rr < 2; rr++) {
            int r = brow + rr * 64;
            CPA16(sptr(&Bs[r * PMK + bcol]), Wt + (size_t)(n0 + r) * CCH + s * 16 + bcol);
        }
        CPCOMMIT();
    }
    for (int kt = 0; kt < NT; kt++) {
        CPWAIT1();
        __syncthreads();
        const float* Ab = smem + (kt % 3) * QKV_STG;
        const float* Bb = Ab + 16 * PKM;
        unsigned af[2][4][4], bf[2][4][2];
        LOAD_AF_KM(af[0], Ab, 0, wm);
        LOAD_BF_MK(bf[0], Bb, 0, wn);
        LOAD_AF_KM(af[1], Ab, 8, wm);
        LOAD_BF_MK(bf[1], Bb, 8, wn);
        MMA_ALL8(acc, af[0], bf[0]);
        MMA_ALL8(acc, af[1], bf[1]);
        int nk = kt + 2;
        if (nk < NT) {
            float* As = smem + (nk % 3) * QKV_STG;
            float* Bs = As + 16 * PKM;
            #pragma unroll
            for (int rr = 0; rr < 2; rr++) {
                int r = arow + rr * 8;
                CPA16(sptr(&As[r * PKM + acol]), Ag + (size_t)(nk * 16 + r) * HW + acol);
            }
            #pragma unroll
            for (int rr = 0; rr < 2; rr++) {
                int r = brow + rr * 64;
                CPA16(sptr(&Bs[r * PMK + bcol]), Wt + (size_t)(n0 + r) * CCH + nk * 16 + bcol);
            }
        }
        CPCOMMIT();
    }
    if (which == 2) {
        float* Vt = g_vt + (size_t)b * CCH * HW;
        #pragma unroll
        for (int mi = 0; mi < 4; mi++)
            #pragma unroll
            for (int nj = 0; nj < 4; nj++) {
                int r = m0 + wm + mi * 16 + g;
                int c = n0 + wn + nj * 8 + 2 * tig;
                float bv0 = bias[c], bv1 = bias[c + 1];
                Vt[(size_t)c * HW + r]           = acc[mi][nj][0] + bv0;
                Vt[(size_t)(c + 1) * HW + r]     = acc[mi][nj][1] + bv1;
                Vt[(size_t)c * HW + r + 8]       = acc[mi][nj][2] + bv0;
                Vt[(size_t)(c + 1) * HW + r + 8] = acc[mi][nj][3] + bv1;
            }
    } else {
        float* Cp = (which == 0 ? g_q : g_k) + (size_t)b * HW * CCH;
        #pragma unroll
        for (int mi = 0; mi < 4; mi++)
            #pragma unroll
            for (int nj = 0; nj < 4; nj++) {
                int r = m0 + wm + mi * 16 + g;
                int c = n0 + wn + nj * 8 + 2 * tig;
                float bv0 = bias[c], bv1 = bias[c + 1];
                *(float2*)&Cp[(size_t)r * CCH + c] =
                    make_float2(acc[mi][nj][0] + bv0, acc[mi][nj][1] + bv1);
                *(float2*)&Cp[(size_t)(r + 8) * CCH + c] =
                    make_float2(acc[mi][nj][2] + bv0, acc[mi][nj][3] + bv1);
            }
    }
}

// -------- Scores (transposed): E'[j,i] = exp(scale * K_j . Q_i) -> bf16 ------
__global__ __launch_bounds__(256, 2)
void scores_mma_kernel() {
    extern __shared__ float smem[];
    int b = blockIdx.z;
    const float* Ag = g_k + (size_t)b * HW * CCH + (size_t)blockIdx.x * 128 * CCH; // m = j
    const float* Bg = g_q + (size_t)b * HW * CCH + (size_t)blockIdx.y * 128 * CCH; // n = i
    int tid = threadIdx.x;
    int lane = tid & 31, warp = tid >> 5;
    int g = lane >> 2, tig = lane & 3;
    int wm = (warp >> 2) * 64, wn = (warp & 3) * 32;
    int brow = tid >> 2, bcol = (tid & 3) << 2;

    float acc[4][4][4];
    #pragma unroll
    for (int i = 0; i < 4; i++)
        #pragma unroll
        for (int j = 0; j < 4; j++)
            #pragma unroll
            for (int t = 0; t < 4; t++) acc[i][j][t] = 0.f;

    const int NT = CCH / 16;
    #pragma unroll
    for (int s = 0; s < 2; s++) {
        float* As = smem + s * SC_STG;
        float* Bs = As + 128 * PMK;
        #pragma unroll
        for (int rr = 0; rr < 2; rr++) {
            int r = brow + rr * 64;
            CPA16(sptr(&As[r * PMK + bcol]), Ag + (size_t)r * CCH + s * 16 + bcol);
            CPA16(sptr(&Bs[r * PMK + bcol]), Bg + (size_t)r * CCH + s * 16 + bcol);
        }
        CPCOMMIT();
    }
    for (int kt = 0; kt < NT; kt++) {
        CPWAIT1();
        __syncthreads();
        const float* Ab = smem + (kt % 3) * SC_STG;
        const float* Bb = Ab + 128 * PMK;
        unsigned af[2][4][4], bf[2][4][2];
        LOAD_AF_MK(af[0], Ab, 0, wm);
        LOAD_BF_MK(bf[0], Bb, 0, wn);
        LOAD_AF_MK(af[1], Ab, 8, wm);
        LOAD_BF_MK(bf[1], Bb, 8, wn);
        MMA_ALL8(acc, af[0], bf[0]);
        MMA_ALL8(acc, af[1], bf[1]);
        int nk = kt + 2;
        if (nk < NT) {
            float* As = smem + (nk % 3) * SC_STG;
            float* Bs = As + 128 * PMK;
            #pragma unroll
            for (int rr = 0; rr < 2; rr++) {
                int r = brow + rr * 64;
                CPA16(sptr(&As[r * PMK + bcol]), Ag + (size_t)r * CCH + nk * 16 + bcol);
                CPA16(sptr(&Bs[r * PMK + bcol]), Bg + (size_t)r * CCH + nk * 16 + bcol);
            }
        }
        CPCOMMIT();
    }
    const float scale = 0.04419417382415922f;   // 512^-0.5
    __nv_bfloat16* Cp = g_s + (size_t)b * HW * HW;
    int m0 = blockIdx.x * 128, n0 = blockIdx.y * 128;
    #pragma unroll
    for (int mi = 0; mi < 4; mi++)
        #pragma unroll
        for (int nj = 0; nj < 4; nj++) {
            int r = m0 + wm + mi * 16 + g;
            int c = n0 + wn + nj * 8 + 2 * tig;
            *(__nv_bfloat162*)&Cp[(size_t)r * HW + c] =
                __floats2bfloat162_rn(__expf(acc[mi][nj][0] * scale),
                                      __expf(acc[mi][nj][1] * scale));
            *(__nv_bfloat162*)&Cp[(size_t)(r + 8) * HW + c] =
                __floats2bfloat162_rn(__expf(acc[mi][nj][2] * scale),
                                      __expf(acc[mi][nj][3] * scale));
        }
}

// ------- column sums of E' (over j) stage 1: partial sums --------------------
__global__ void zcolsum_kernel() {
    int b = blockIdx.z;
    const __nv_bfloat162* S = (const __nv_bfloat162*)(g_s + (size_t)b * HW * HW);
    int t = threadIdx.x;
    size_t rowstride = HW / 2;
    const __nv_bfloat162* p = S + (size_t)(blockIdx.y * 512) * rowstride
                                + blockIdx.x * 256 + t;
    float sx = 0.f, sy = 0.f;
    #pragma unroll 8
    for (int j = 0; j < 512; j++) {
        float2 v = __bfloat1622float2(*p);
        sx += v.x; sy += v.y;
        p += rowstride;
    }
    float* zp = g_zp + ((size_t)(b * 8 + blockIdx.y)) * HW
              + (size_t)(blockIdx.x * 256 + t) * 2;
    zp[0] = sx; zp[1] = sy;
}

// ------- stage 2: combine 8 partials, reciprocal -----------------------------
__global__ void zfin_kernel() {
    int idx = blockIdx.x * 256 + threadIdx.x;   // < BATCH*HW
    int b = idx >> 12, i = idx & (HW - 1);
    float s = 0.f;
    #pragma unroll
    for (int p = 0; p < 8; p++) s += g_zp[((size_t)(b * 8 + p)) * HW + i];
    g_z[idx] = 1.f / s;
}

// ------- V-hat: g_vb[c][i] = bf16(g_vt[c][i] * g_z[i]) -----------------------
__global__ void vscale_kernel() {
    size_t idx4 = (size_t)blockIdx.x * 256 + threadIdx.x;
    int b = (int)(idx4 / ((size_t)CCH * (HW / 4)));
    size_t rem = idx4 - (size_t)b * CCH * (HW / 4);
    int i4 = (int)(rem % (HW / 4));
    float4 v = ((const float4*)g_vt)[idx4];
    float4 z = ((const float4*)g_z)[(size_t)b * (HW / 4) + i4];
    __nv_bfloat162* o = ((__nv_bfloat162*)g_vb) + idx4 * 2;
    o[0] = __floats2bfloat162_rn(v.x * z.x, v.y * z.y);
    o[1] = __floats2bfloat162_rn(v.z * z.z, v.w * z.w);
}

// ------ O GEMM (bf16): O[j,c] = sum_i E'[j,i] * Vhat[c,i] --------------------
__global__ __launch_bounds__(256, 2)
void o_bf16_kernel() {
    extern __shared__ unsigned osm[];
    int b = blockIdx.z;
    const __nv_bfloat16* Ag = g_s  + (size_t)b * HW * HW + (size_t)(blockIdx.x * 128) * HW;
    const __nv_bfloat16* Bg = g_vb + (size_t)b * CCH * HW + (size_t)(blockIdx.y * 128) * HW;
    int tid = threadIdx.x;
    int lane = tid & 31, warp = tid >> 5;
    int g = lane >> 2, tig = lane & 3;
    int wm = (warp >> 2) * 64, wn = (warp & 3) * 32;
    int lrow = tid >> 1, lh = tid & 1;          // 2 x 16B chunks per thread per operand
    uint32_t sbase = sptr(osm);

    float acc[4][4][4];
    #pragma unroll
    for (int i = 0; i < 4; i++)
        #pragma unroll
        for (int j = 0; j < 4; j++)
            #pragma unroll
            for (int t = 0; t < 4; t++) acc[i][j][t] = 0.f;

    const int NC = HW / 32;
    #pragma unroll
    for (int s = 0; s < 2; s++) {
        uint32_t st = sbase + s * O_STG_BYTES;
        const __nv_bfloat16* as = Ag + (size_t)lrow * HW + s * 32 + lh * 16;
        const __nv_bfloat16* bs = Bg + (size_t)lrow * HW + s * 32 + lh * 16;
        CPA16(st + lrow * 80 + lh * 32,              as);
        CPA16(st + lrow * 80 + lh * 32 + 16,         as + 8);
        CPA16(st + 10240 + lrow * 80 + lh * 32,      bs);
        CPA16(st + 10240 + lrow * 80 + lh * 32 + 16, bs + 8);
        CPCOMMIT();
    }
    for (int kt = 0; kt < NC; kt++) {
        CPWAIT1();
        __syncthreads();
        const unsigned* At = osm + (kt % 3) * O_STG_WORDS;
        const unsigned* Bt = At + 128 * OROWW;
        #pragma unroll
        for (int kk = 0; kk < 2; kk++) {
            unsigned af[4][4], bf[4][2];
            #pragma unroll
            for (int mi = 0; mi < 4; mi++) {
                int mb = wm + mi * 16 + g;
                af[mi][0] = At[mb * OROWW + kk * 8 + tig];
                af[mi][1] = At[(mb + 8) * OROWW + kk * 8 + tig];
                af[mi][2] = At[mb * OROWW + kk * 8 + tig + 4];
                af[mi][3] = At[(mb + 8) * OROWW + kk * 8 + tig + 4];
            }
            #pragma unroll
            for (int nj = 0; nj < 4; nj++) {
                int nb = wn + nj * 8 + g;
                bf[nj][0] = Bt[nb * OROWW + kk * 8 + tig];
                bf[nj][1] = Bt[nb * OROWW + kk * 8 + tig + 4];
            }
            #pragma unroll
            for (int mi = 0; mi < 4; mi++)
                #pragma unroll
                for (int nj = 0; nj < 4; nj++) mma16(acc[mi][nj], af[mi], bf[nj]);
        }
        int nk = kt + 2;
        if (nk < NC) {
            uint32_t st = sbase + (nk % 3) * O_STG_BYTES;
            const __nv_bfloat16* as = Ag + (size_t)lrow * HW + nk * 32 + lh * 16;
            const __nv_bfloat16* bs = Bg + (size_t)lrow * HW + nk * 32 + lh * 16;
            CPA16(st + lrow * 80 + lh * 32,              as);
            CPA16(st + lrow * 80 + lh * 32 + 16,         as + 8);
            CPA16(st + 10240 + lrow * 80 + lh * 32,      bs);
            CPA16(st + 10240 + lrow * 80 + lh * 32 + 16, bs + 8);
        }
        CPCOMMIT();
    }
    float* Cp = g_o + (size_t)b * HW * CCH;
    int m0 = blockIdx.x * 128, n0 = blockIdx.y * 128;
    #pragma unroll
    for (int mi = 0; mi < 4; mi++)
        #pragma unroll
        for (int nj = 0; nj < 4; nj++) {
            int r = m0 + wm + mi * 16 + g;
            int c = n0 + wn + nj * 8 + 2 * tig;
            *(float2*)&Cp[(size_t)r * CCH + c] =
                make_float2(acc[mi][nj][0], acc[mi][nj][1]);
            *(float2*)&Cp[(size_t)(r + 8) * CCH + c] =
                make_float2(acc[mi][nj][2], acc[mi][nj][3]);
        }
}

// ------ Proj+residual: out[o,m] = x[o,m] + sum_c O[m,c]Wp[o,c]+bp[o] ---------
__global__ __launch_bounds__(256, 2)
void proj_mma_kernel(const float* __restrict__ Wp, const float* __restrict__ bp,
                     const float* __restrict__ x, float* __restrict__ out) {
    extern __shared__ float smem[];
    int b = blockIdx.z;
    const float* Ag = g_o + (size_t)b * HW * CCH + (size_t)blockIdx.x * 128 * CCH;
    const float* xb = x   + (size_t)b * CCH * HW;
    float* ob = out + (size_t)b * CCH * HW;
    int n0 = blockIdx.y * 128, m0 = blockIdx.x * 128;
    int tid = threadIdx.x;
    int lane = tid & 31, warp = tid >> 5;
    int g = lane >> 2, tig = lane & 3;
    int wm = (warp >> 2) * 64, wn = (warp & 3) * 32;
    int brow = tid >> 2, bcol = (tid & 3) << 2;

    float acc[4][4][4];
    #pragma unroll
    for (int i = 0; i < 4; i++)
        #pragma unroll
        for (int j = 0; j < 4; j++)
            #pragma unroll
            for (int t = 0; t < 4; t++) acc[i][j][t] = 0.f;

    const int NT = CCH / 16;
    #pragma unroll
    for (int s = 0; s < 2; s++) {
        float* As = smem + s * SC_STG;
        float* Bs = As + 128 * PMK;
        #pragma unroll
        for (int rr = 0; rr < 2; rr++) {
            int r = brow + rr * 64;
            CPA16(sptr(&As[r * PMK + bcol]), Ag + (size_t)r * CCH + s * 16 + bcol);
            CPA16(sptr(&Bs[r * PMK + bcol]), Wp + (size_t)(n0 + r) * CCH + s * 16 + bcol);
        }
        CPCOMMIT();
    }
    for (int kt = 0; kt < NT; kt++) {
        CPWAIT1();
        __syncthreads();
        const float* Ab = smem + (kt % 3) * SC_STG;
        const float* Bb = Ab + 128 * PMK;
        unsigned af[2][4][4], bf[2][4][2];
        LOAD_AF_MK(af[0], Ab, 0, wm);
        LOAD_BF_MK(bf[0], Bb, 0, wn);
        LOAD_AF_MK(af[1], Ab, 8, wm);
        LOAD_BF_MK(bf[1], Bb, 8, wn);
        MMA_ALL8(acc, af[0], bf[0]);
        MMA_ALL8(acc, af[1], bf[1]);
        int nk = kt + 2;
        if (nk < NT) {
            float* As = smem + (nk % 3) * SC_STG;
            float* Bs = As + 128 * PMK;
            #pragma unroll
            for (int rr = 0; rr < 2; rr++) {
                int r = brow + rr * 64;
                CPA16(sptr(&As[r * PMK + bcol]), Ag + (size_t)r * CCH + nk * 16 + bcol);
                CPA16(sptr(&Bs[r * PMK + bcol]), Wp + (size_t)(n0 + r) * CCH + nk * 16 + bcol);
            }
        }
        CPCOMMIT();
    }
    #pragma unroll
    for (int nj = 0; nj < 4; nj++) {
        int c0 = n0 + wn + nj * 8 + 2 * tig;
        float bv0 = bp[c0], bv1 = bp[c0 + 1];
        #pragma unroll
        for (int mi = 0; mi < 4; mi++) {
            int r = m0 + wm + mi * 16 + g;
            ob[(size_t)c0 * HW + r]           = xb[(size_t)c0 * HW + r]           + acc[mi][nj][0] + bv0;
            ob[(size_t)(c0 + 1) * HW + r]     = xb[(size_t)(c0 + 1) * HW + r]     + acc[mi][nj][1] + bv1;
            ob[(size_t)c0 * HW + r + 8]       = xb[(size_t)c0 * HW + r + 8]       + acc[mi][nj][2] + bv0;
            ob[(size_t)(c0 + 1) * HW + r + 8] = xb[(size_t)(c0 + 1) * HW + r + 8] + acc[mi][nj][3] + bv1;
        }
    }
}

// ------------------------------ launch ---------------------------------------
extern "C" void kernel_launch(void* const* d_in, const int* in_sizes, int n_in,
                              void* d_out, int out_size) {
    const float* x  = (const float*)d_in[0];
    const float* nw = (const float*)d_in[1];
    const float* nb = (const float*)d_in[2];
    const float* wq = (const float*)d_in[3];
    const float* bq = (const float*)d_in[4];
    const float* wk = (const float*)d_in[5];
    const float* bk = (const float*)d_in[6];
    const float* wv = (const float*)d_in[7];
    const float* bv = (const float*)d_in[8];
    const float* wp = (const float*)d_in[9];
    const float* bp = (const float*)d_in[10];
    float* out = (float*)d_out;

    static int attr_done = 0;
    if (!attr_done) {
        cudaFuncSetAttribute(qkv_mma_kernel,
                             cudaFuncAttributeMaxDynamicSharedMemorySize, QKV_DYN);
        cudaFuncSetAttribute(scores_mma_kernel,
                             cudaFuncAttributeMaxDynamicSharedMemorySize, SC_DYN);
        cudaFuncSetAttribute(o_bf16_kernel,
                             cudaFuncAttributeMaxDynamicSharedMemorySize, O_DYN_B);
        cudaFuncSetAttribute(proj_mma_kernel,
                             cudaFuncAttributeMaxDynamicSharedMemorySize, SC_DYN);
        attr_done = 1;
    }

    groupnorm_kernel<<<BATCH * NGRP, 256>>>(x, nw, nb);

    dim3 gqkv(HW / 128, 3 * CCH / 128, BATCH);  // 32 x 12 x 2
    qkv_mma_kernel<<<gqkv, 256, QKV_DYN>>>(wq, bq, wk, bk, wv, bv);

    dim3 gsc(HW / 128, HW / 128, BATCH);        // 32 x 32 x 2
    scores_mma_kernel<<<gsc, 256, SC_DYN>>>();

    dim3 gzc(HW / 512, 8, BATCH);               // 8 x 8 x 2
    zcolsum_kernel<<<gzc, 256>>>();
    zfin_kernel<<<(BATCH * HW) / 256, 256>>>();
    vscale_kernel<<<(BATCH * CCH * HW) / (4 * 256), 256>>>();

    dim3 go(HW / 128, CCH / 128, BATCH);        // 32 x 4 x 2
    o_bf16_kernel<<<go, 256, O_DYN_B>>>();

    proj_mma_kernel<<<go, 256, SC_DYN>>>(wp, bp, x, out);
}